// round 10
// baseline (speedup 1.0000x reference)
#include <cuda_runtime.h>
#include <cstdint>
#include <math.h>

#define Bdim 2
#define Tdim 2048
#define HID 2048
#define NH 32
#define NKV 8
#define HD 64
#define BT (Bdim * Tdim)   // 4096

typedef unsigned short ushort_t;

// ---------------- scratch (device globals; no allocations allowed) ----------
__device__ float g_qt[(size_t)BT * NH * HD];
__device__ float g_kt[(size_t)BT * NKV * HD];
__device__ float g_vt[(size_t)BT * NKV * HD];
__device__ __align__(16) ushort_t g_hh[(size_t)BT * HID];
__device__ __align__(16) ushort_t g_hl[(size_t)BT * HID];
__device__ __align__(16) ushort_t g_wqh[(size_t)NH * HD * HID];
__device__ __align__(16) ushort_t g_wql[(size_t)NH * HD * HID];
__device__ __align__(16) ushort_t g_wkh[(size_t)NKV * HD * HID];
__device__ __align__(16) ushort_t g_wkl[(size_t)NKV * HD * HID];
__device__ __align__(16) ushort_t g_wvh[(size_t)NKV * HD * HID];
__device__ __align__(16) ushort_t g_wvl[(size_t)NKV * HD * HID];
__device__ __align__(16) ushort_t g_woh[(size_t)HID * NH * HD];
__device__ __align__(16) ushort_t g_wol[(size_t)HID * NH * HD];
__device__ __align__(16) ushort_t g_qh[(size_t)Bdim * NH  * Tdim * HD];
__device__ __align__(16) ushort_t g_ql[(size_t)Bdim * NH  * Tdim * HD];
__device__ __align__(16) ushort_t g_kh[(size_t)Bdim * NKV * Tdim * HD];
__device__ __align__(16) ushort_t g_kl[(size_t)Bdim * NKV * Tdim * HD];
__device__ __align__(16) ushort_t g_vh[(size_t)Bdim * NKV * Tdim * HD];
__device__ __align__(16) ushort_t g_vl[(size_t)Bdim * NKV * Tdim * HD];
__device__ __align__(16) ushort_t g_oh[(size_t)BT * NH * HD];
__device__ __align__(16) ushort_t g_ol[(size_t)BT * NH * HD];

// ======================= helpers ============================================
static __device__ __forceinline__ uint32_t smem_u32(const void* p) {
    uint32_t a;
    asm("{ .reg .u64 t; cvta.to.shared.u64 t, %1; cvt.u32.u64 %0, t; }"
        : "=r"(a) : "l"(p));
    return a;
}

static __device__ __forceinline__ void ldm4(uint32_t* r, uint32_t addr) {
    asm volatile("ldmatrix.sync.aligned.m8n8.x4.shared.b16 {%0,%1,%2,%3}, [%4];"
                 : "=r"(r[0]), "=r"(r[1]), "=r"(r[2]), "=r"(r[3]) : "r"(addr));
}

static __device__ __forceinline__ void ldm4t(uint32_t* r, uint32_t addr) {
    asm volatile("ldmatrix.sync.aligned.m8n8.x4.trans.shared.b16 {%0,%1,%2,%3}, [%4];"
                 : "=r"(r[0]), "=r"(r[1]), "=r"(r[2]), "=r"(r[3]) : "r"(addr));
}

static __device__ __forceinline__ void mma16816(float* c, const uint32_t* a,
                                                uint32_t b0, uint32_t b1) {
    asm volatile("mma.sync.aligned.m16n8k16.row.col.f32.bf16.bf16.f32 "
                 "{%0,%1,%2,%3}, {%4,%5,%6,%7}, {%8,%9}, {%0,%1,%2,%3};"
                 : "+f"(c[0]), "+f"(c[1]), "+f"(c[2]), "+f"(c[3])
                 : "r"(a[0]), "r"(a[1]), "r"(a[2]), "r"(a[3]), "r"(b0), "r"(b1));
}

static __device__ __forceinline__ uint32_t pack_hi(float a, float b) {
    return __byte_perm(__float_as_uint(a), __float_as_uint(b), 0x7632);
}
static __device__ __forceinline__ uint32_t pack_lo(float a, float b) {
    float ra = a - __uint_as_float(__float_as_uint(a) & 0xFFFF0000u);
    float rb = b - __uint_as_float(__float_as_uint(b) & 0xFFFF0000u);
    uint32_t r;
    asm("cvt.rn.satfinite.bf16x2.f32 %0, %1, %2;" : "=r"(r) : "f"(rb), "f"(ra));
    return r;
}

static __device__ __forceinline__ float ex2(float x) {
    float r;
    asm("ex2.approx.f32 %0, %1;" : "=f"(r) : "f"(x));
    return r;
}

static __device__ __forceinline__ void split_store(float x, ushort_t* ph,
                                                   ushort_t* pl) {
    uint32_t u = __float_as_uint(x);
    *ph = (ushort_t)(u >> 16);
    float lo = x - __uint_as_float(u & 0xFFFF0000u);
    ushort_t ls;
    asm("cvt.rn.satfinite.bf16.f32 %0, %1;" : "=h"(ls) : "f"(lo));
    *pl = ls;
}

#define CP_ASYNC(dst, src) \
    asm volatile("cp.async.cg.shared.global [%0], [%1], 16;" \
                 :: "r"(dst), "l"(src) : "memory")
#define CP_COMMIT() asm volatile("cp.async.commit_group;" ::: "memory")
#define CP_WAIT1() asm volatile("cp.async.wait_group 1;" ::: "memory")
#define CP_WAIT0() asm volatile("cp.async.wait_group 0;" ::: "memory")

// ---------------- input pre-split ------------------------------------------
__global__ __launch_bounds__(256) void split_f32(const float* __restrict__ src,
                                                 ushort_t* __restrict__ hi,
                                                 ushort_t* __restrict__ lo,
                                                 int n4) {
    int i = blockIdx.x * blockDim.x + threadIdx.x;
    if (i < n4) {
        float4 f = ((const float4*)src)[i];
        ((uint2*)hi)[i] = make_uint2(pack_hi(f.x, f.y), pack_hi(f.z, f.w));
        ((uint2*)lo)[i] = make_uint2(pack_lo(f.x, f.y), pack_lo(f.z, f.w));
    }
}

// =============== mma.sync GEMM (pre-split inputs, cp.async pipeline) ========
#define G_ROWB 80
#define G_TILE 10240
#define G_STAGE_B (4 * G_TILE)
#define G_SMEM (2 * G_STAGE_B + 128)

__global__ __launch_bounds__(256, 2) void gemm_mma_s(
    const ushort_t* __restrict__ Ah, const ushort_t* __restrict__ Al,
    const ushort_t* __restrict__ Bh, const ushort_t* __restrict__ Bl,
    float* __restrict__ C, int M, int N, int K) {
    extern __shared__ char dsm[];
    const uint32_t tile = (smem_u32(dsm) + 127u) & ~127u;

    const int tid = threadIdx.x;
    const int wid = tid >> 5;
    const int lane = tid & 31;
    const int wm = wid & 3;
    const int wn = wid >> 2;
    const int bm = blockIdx.y * 128;
    const int bn = blockIdx.x * 128;

    const int row = tid >> 1;
    const int half = tid & 1;
    const ushort_t* pAh = Ah + (size_t)(bm + row) * K + half * 16;
    const ushort_t* pAl = Al + (size_t)(bm + row) * K + half * 16;
    const ushort_t* pBh = Bh + (size_t)(bn + row) * K + half * 16;
    const ushort_t* pBl = Bl + (size_t)(bn + row) * K + half * 16;
    const uint32_t s_row = (uint32_t)(row * G_ROWB + half * 32);

    const int r8 = lane & 7, sub = lane >> 3;
    const uint32_t a_off = (uint32_t)((wm * 32 + r8 + (sub & 1) * 8) * G_ROWB +
                                      (sub >> 1) * 16);
    const uint32_t b_off = (uint32_t)((wn * 64 + r8 + (sub >> 1) * 8) * G_ROWB +
                                      (sub & 1) * 16);

    float acc[2][8][4];
#pragma unroll
    for (int i = 0; i < 2; i++)
#pragma unroll
        for (int j = 0; j < 8; j++)
#pragma unroll
            for (int q = 0; q < 4; q++) acc[i][j][q] = 0.f;

    const int nch = K >> 5;

#define G_ISSUE(chunk, sb) do {                                               \
    const int _k0 = (chunk) << 5;                                             \
    CP_ASYNC((sb) + s_row,                   pAh + _k0);                      \
    CP_ASYNC((sb) + s_row + 16,              pAh + _k0 + 8);                  \
    CP_ASYNC((sb) + G_TILE + s_row,          pAl + _k0);                      \
    CP_ASYNC((sb) + G_TILE + s_row + 16,     pAl + _k0 + 8);                  \
    CP_ASYNC((sb) + 2 * G_TILE + s_row,      pBh + _k0);                      \
    CP_ASYNC((sb) + 2 * G_TILE + s_row + 16, pBh + _k0 + 8);                  \
    CP_ASYNC((sb) + 3 * G_TILE + s_row,      pBl + _k0);                      \
    CP_ASYNC((sb) + 3 * G_TILE + s_row + 16, pBl + _k0 + 8);                  \
} while (0)

    G_ISSUE(0, tile);              CP_COMMIT();
    G_ISSUE(1, tile + G_STAGE_B);  CP_COMMIT();

    for (int i = 0; i < nch; i++) {
        const uint32_t cur = tile + (uint32_t)(i & 1) * G_STAGE_B;
        if (i + 1 < nch) { CP_WAIT1(); } else { CP_WAIT0(); }
        __syncthreads();

#pragma unroll
        for (int ks = 0; ks < 2; ks++) {
            uint32_t ah[8], al[8];
            const uint32_t ka = cur + a_off + ks * 32;
            ldm4(ah,     ka);
            ldm4(ah + 4, ka + 16 * G_ROWB);
            ldm4(al,     ka + G_TILE);
            ldm4(al + 4, ka + G_TILE + 16 * G_ROWB);
#pragma unroll
            for (int g = 0; g < 4; g++) {
                uint32_t bh[4], bl[4];
                const uint32_t kb = cur + 2 * G_TILE + b_off + ks * 32 +
                                    g * (16 * G_ROWB);
                ldm4(bh, kb);
                ldm4(bl, kb + G_TILE);
#pragma unroll
                for (int ms = 0; ms < 2; ms++) {
                    mma16816(acc[ms][2 * g],     ah + 4 * ms, bh[0], bh[1]);
                    mma16816(acc[ms][2 * g + 1], ah + 4 * ms, bh[2], bh[3]);
                    mma16816(acc[ms][2 * g],     ah + 4 * ms, bl[0], bl[1]);
                    mma16816(acc[ms][2 * g + 1], ah + 4 * ms, bl[2], bl[3]);
                    mma16816(acc[ms][2 * g],     al + 4 * ms, bh[0], bh[1]);
                    mma16816(acc[ms][2 * g + 1], al + 4 * ms, bh[2], bh[3]);
                }
            }
        }
        __syncthreads();
        if (i + 2 < nch) {
            G_ISSUE(i + 2, cur);
            CP_COMMIT();
        }
    }
#undef G_ISSUE

    const int trow = lane >> 2;
    const int tcol = (lane & 3) * 2;
#pragma unroll
    for (int ms = 0; ms < 2; ms++) {
#pragma unroll
        for (int nf = 0; nf < 8; nf++) {
            const int r = bm + wm * 32 + ms * 16 + trow;
            const int c = bn + wn * 64 + nf * 8 + tcol;
            *(float2*)(C + (size_t)r * N + c) =
                make_float2(acc[ms][nf][0], acc[ms][nf][1]);
            *(float2*)(C + (size_t)(r + 8) * N + c) =
                make_float2(acc[ms][nf][2], acc[ms][nf][3]);
        }
    }
}

// ---------------- RoPE + head transpose + bf16 split ------------------------
__global__ __launch_bounds__(256) void rope_split(const float* __restrict__ cosp,
                                                  const float* __restrict__ sinp) {
    const int token = blockIdx.x;
    const int b = token / Tdim;
    const int t = token % Tdim;
    __shared__ float cs[HD], sn[HD];
    if (threadIdx.x < HD) {
        cs[threadIdx.x] = cosp[(size_t)token * HD + threadIdx.x];
        sn[threadIdx.x] = sinp[(size_t)token * HD + threadIdx.x];
    }
    __syncthreads();

    const float qsc = 0.125f * 1.4426950408889634f;
    for (int p = threadIdx.x; p < NH * 32; p += 256) {
        const int hh = p >> 5;
        const int d  = p & 31;
        const size_t src = (size_t)token * (NH * HD) + hh * HD + d;
        float x1 = g_qt[src];
        float x2 = g_qt[src + 32];
        float c = cs[d], s = sn[d];
        const size_t base = ((size_t)(b * NH + hh) * Tdim + t) * HD;
        float y1 = (x1 * c - x2 * s) * qsc;
        float y2 = (x2 * c + x1 * s) * qsc;
        split_store(y1, &g_qh[base + d],      &g_ql[base + d]);
        split_store(y2, &g_qh[base + d + 32], &g_ql[base + d + 32]);
    }
    for (int p = threadIdx.x; p < NKV * 32; p += 256) {
        const int hh = p >> 5;
        const int d  = p & 31;
        const size_t src = (size_t)token * (NKV * HD) + hh * HD + d;
        float x1 = g_kt[src];
        float x2 = g_kt[src + 32];
        float c = cs[d], s = sn[d];
        const size_t base = ((size_t)(b * NKV + hh) * Tdim + t) * HD;
        float y1 = x1 * c - x2 * s;
        float y2 = x2 * c + x1 * s;
        split_store(y1, &g_kh[base + d],      &g_kl[base + d]);
        split_store(y2, &g_kh[base + d + 32], &g_kl[base + d + 32]);
    }
    for (int e = threadIdx.x; e < NKV * HD; e += 256) {
        const int hh = e >> 6;
        const int d  = e & 63;
        float v = g_vt[(size_t)token * (NKV * HD) + e];
        const size_t base = ((size_t)(b * NKV + hh) * Tdim + t) * HD;
        split_store(v, &g_vh[base + d], &g_vl[base + d]);
    }
}

// ---------------- Flash attention (tensor cores, cp.async K/V pipeline) -----
// Br=128, Bc=64, 256 threads (8 warps). Q resident; K/V double-buffered.
// smem bytes: Qh 0, Ql 18432; stage s at 36864 + s*36864:
//   Kh +0, Kl +9216, Vh +18432, Vl +27648 (each 64 x 144B).
#define FB 144
#define FA_STAGE_B 36864
#define FA_SMEM (36864 + 2 * FA_STAGE_B)   // 110592

__global__ __launch_bounds__(256, 2) void flash_mma() {
    extern __shared__ ushort_t fsm[];
    const uint32_t s0 = smem_u32(fsm);
    const uint32_t sQh = s0, sQl = s0 + 18432;

    const int tid = threadIdx.x;
    const int lane = tid & 31;
    const int w = tid >> 5;
    const int qtile = (int)gridDim.x - 1 - (int)blockIdx.x;  // big first
    const int bh = blockIdx.y;
    const int b = bh / NH;
    const int h = bh % NH;
    const int kvh = h / (NH / NKV);

    const ushort_t* qhp = g_qh + ((size_t)bh * Tdim + qtile * 128) * HD;
    const ushort_t* qlp = g_ql + ((size_t)bh * Tdim + qtile * 128) * HD;
    const size_t kvbase = (size_t)(b * NKV + kvh) * Tdim * HD;
    const ushort_t* pkh = g_kh + kvbase;
    const ushort_t* pkl = g_kl + kvbase;
    const ushort_t* pvh = g_vh + kvbase;
    const ushort_t* pvl = g_vl + kvbase;

    // per-thread load mapping for one 64x64 tile: 2 x 16B per array
    const uint32_t d0 = (uint32_t)((tid >> 3) * FB + (tid & 7) * 16);
    const uint32_t d1 = (uint32_t)(((tid + 256) >> 3) * FB + (tid & 7) * 16);
    const uint32_t g0 = (uint32_t)((tid >> 3) * HD + (tid & 7) * 8);
    const uint32_t g1 = (uint32_t)(((tid + 256) >> 3) * HD + (tid & 7) * 8);

#define FA_ISSUE(kt, stg) do {                                                \
    const uint32_t _sb = s0 + 36864 + (uint32_t)(stg) * FA_STAGE_B;           \
    const size_t _go = (size_t)(kt) * 64 * HD;                                \
    CP_ASYNC(_sb + d0,         pkh + _go + g0);                               \
    CP_ASYNC(_sb + d1,         pkh + _go + g1);                               \
    CP_ASYNC(_sb + 9216 + d0,  pkl + _go + g0);                               \
    CP_ASYNC(_sb + 9216 + d1,  pkl + _go + g1);                               \
    CP_ASYNC(_sb + 18432 + d0, pvh + _go + g0);                               \
    CP_ASYNC(_sb + 18432 + d1, pvh + _go + g1);                               \
    CP_ASYNC(_sb + 27648 + d0, pvl + _go + g0);                               \
    CP_ASYNC(_sb + 27648 + d1, pvl + _go + g1);                               \
} while (0)

    // prologue: ktmax = 2*qtile+1 >= 1, so tiles 0 and 1 always exist
    FA_ISSUE(0, 0); CP_COMMIT();
    FA_ISSUE(1, 1); CP_COMMIT();

    // stage Q (128x64 bf16 x2)
#pragma unroll
    for (int j = 0; j < 4; j++) {
        const int idx = tid + j * 256;
        const int qr = idx >> 3;
        const int qc = idx & 7;
        *(uint4*)(fsm + qr * 72 + qc * 8)        = *(const uint4*)(qhp + qr * HD + qc * 8);
        *(uint4*)(fsm + 9216 + qr * 72 + qc * 8) = *(const uint4*)(qlp + qr * HD + qc * 8);
    }

    const int r8 = lane & 7, sub = lane >> 3;
    const uint32_t a_off = (uint32_t)((w * 16 + r8 + ((sub & 1) << 3)) * FB +
                                      ((sub >> 1) << 4));
    const uint32_t b_off = (uint32_t)((r8 + ((sub >> 1) << 3)) * FB +
                                      ((sub & 1) << 4));
    const uint32_t v_off = (uint32_t)(((lane & 8) + (lane & 7)) * FB +
                                      (lane >> 4) * 16);

    float m0 = -1e30f, m1 = -1e30f, l0 = 0.f, l1 = 0.f;
    float o[8][4];
#pragma unroll
    for (int t = 0; t < 8; t++)
#pragma unroll
        for (int e = 0; e < 4; e++) o[t][e] = 0.f;

    const int ktmax = 2 * qtile + 1;
    for (int kt = 0; kt <= ktmax; kt++) {
        const uint32_t stg = s0 + 36864 + (uint32_t)(kt & 1) * FA_STAGE_B;
        if (kt < ktmax) { CP_WAIT1(); } else { CP_WAIT0(); }
        __syncthreads();

        // --- S = Q K^T (3x split, base-2 logits) ---
        float sa[8][4];
#pragma unroll
        for (int t = 0; t < 8; t++)
#pragma unroll
            for (int e = 0; e < 4; e++) sa[t][e] = 0.f;

#pragma unroll
        for (int ks = 0; ks < 4; ks++) {
            uint32_t aqh[4], aql[4];
            ldm4(aqh, sQh + a_off + ks * 32);
            ldm4(aql, sQl + a_off + ks * 32);
#pragma unroll
            for (int g = 0; g < 4; g++) {
                uint32_t kbh[4], kbl[4];
                const uint32_t kb = stg + b_off + ks * 32 + g * (16 * FB);
                ldm4(kbh, kb);
                ldm4(kbl, kb + 9216);
                mma16816(sa[2 * g],     aqh, kbh[0], kbh[1]);
                mma16816(sa[2 * g + 1], aqh, kbh[2], kbh[3]);
                mma16816(sa[2 * g],     aqh, kbl[0], kbl[1]);
                mma16816(sa[2 * g + 1], aqh, kbl[2], kbl[3]);
                mma16816(sa[2 * g],     aql, kbh[0], kbh[1]);
                mma16816(sa[2 * g + 1], aql, kbh[2], kbh[3]);
            }
        }

        // --- causal mask (last two tiles only) ---
        if (kt >= 2 * qtile) {
            const int row0 = qtile * 128 + w * 16 + (lane >> 2);
            const int cb = kt * 64 + (lane & 3) * 2;
#pragma unroll
            for (int t = 0; t < 8; t++) {
                const int c0 = cb + t * 8;
                if (c0 > row0)         sa[t][0] = -1e30f;
                if (c0 + 1 > row0)     sa[t][1] = -1e30f;
                if (c0 > row0 + 8)     sa[t][2] = -1e30f;
                if (c0 + 1 > row0 + 8) sa[t][3] = -1e30f;
            }
        }

        // --- online softmax (base 2) ---
        float rm0 = -1e30f, rm1 = -1e30f;
#pragma unroll
        for (int t = 0; t < 8; t++) {
            rm0 = fmaxf(rm0, fmaxf(sa[t][0], sa[t][1]));
            rm1 = fmaxf(rm1, fmaxf(sa[t][2], sa[t][3]));
        }
        rm0 = fmaxf(rm0, __shfl_xor_sync(0xffffffffu, rm0, 1));
        rm0 = fmaxf(rm0, __shfl_xor_sync(0xffffffffu, rm0, 2));
        rm1 = fmaxf(rm1, __shfl_xor_sync(0xffffffffu, rm1, 1));
        rm1 = fmaxf(rm1, __shfl_xor_sync(0xffffffffu, rm1, 2));
        const float mn0 = fmaxf(m0, rm0);
        const float mn1 = fmaxf(m1, rm1);
        const float al0 = ex2(m0 - mn0);
        const float al1 = ex2(m1 - mn1);
        m0 = mn0; m1 = mn1;
        float rs0 = 0.f, rs1 = 0.f;
#pragma unroll
        for (int t = 0; t < 8; t++) {
            sa[t][0] = ex2(sa[t][0] - mn0);
            sa[t][1] = ex2(sa[t][1] - mn0);
            sa[t][2] = ex2(sa[t][2] - mn1);
            sa[t][3] = ex2(sa[t][3] - mn1);
            rs0 += sa[t][0] + sa[t][1];
            rs1 += sa[t][2] + sa[t][3];
        }
        rs0 += __shfl_xor_sync(0xffffffffu, rs0, 1);
        rs0 += __shfl_xor_sync(0xffffffffu, rs0, 2);
        rs1 += __shfl_xor_sync(0xffffffffu, rs1, 1);
        rs1 += __shfl_xor_sync(0xffffffffu, rs1, 2);
        l0 = l0 * al0 + rs0;
        l1 = l1 * al1 + rs1;
#pragma unroll
        for (int t = 0; t < 8; t++) {
            o[t][0] *= al0; o[t][1] *= al0;
            o[t][2] *= al1; o[t][3] *= al1;
        }

        // --- repack P (hi + lo split, register-only) ---
        uint32_t ph[4][4], pl[4][4];
#pragma unroll
        for (int kc = 0; kc < 4; kc++) {
            const int t0 = 2 * kc, t1 = 2 * kc + 1;
            ph[kc][0] = pack_hi(sa[t0][0], sa[t0][1]);
            ph[kc][1] = pack_hi(sa[t0][2], sa[t0][3]);
            ph[kc][2] = pack_hi(sa[t1][0], sa[t1][1]);
            ph[kc][3] = pack_hi(sa[t1][2], sa[t1][3]);
            pl[kc][0] = pack_lo(sa[t0][0], sa[t0][1]);
            pl[kc][1] = pack_lo(sa[t0][2], sa[t0][3]);
            pl[kc][2] = pack_lo(sa[t1][0], sa[t1][1]);
            pl[kc][3] = pack_lo(sa[t1][2], sa[t1][3]);
        }

        // --- O += P V (3x split) ---
        const uint32_t sVh = stg + 18432;
#pragma unroll
        for (int kc = 0; kc < 4; kc++) {
#pragma unroll
            for (int tp = 0; tp < 4; tp++) {
                uint32_t vbh[4], vbl[4];
                const uint32_t va = sVh + v_off + kc * (16 * FB) + tp * 32;
                ldm4t(vbh, va);
                ldm4t(vbl, va + 9216);
                mma16816(o[2 * tp],     ph[kc], vbh[0], vbh[1]);
                mma16816(o[2 * tp + 1], ph[kc], vbh[2], vbh[3]);
                mma16816(o[2 * tp],     ph[kc], vbl[0], vbl[1]);
                mma16816(o[2 * tp + 1], ph[kc], vbl[2], vbl[3]);
                mma16816(o[2 * tp],     pl[kc], vbh[0], vbh[1]);
                mma16816(o[2 * tp + 1], pl[kc], vbh[2], vbh[3]);
            }
        }

        __syncthreads();
        if (kt + 2 <= ktmax) {
            FA_ISSUE(kt + 2, kt & 1);
            CP_COMMIT();
        }
    }
#undef FA_ISSUE

    // epilogue: normalize + split-write for the O projection
    const float inv0 = 1.0f / l0;
    const float inv1 = 1.0f / l1;
    const int row0 = qtile * 128 + w * 16 + (lane >> 2);
    const int colb = (lane & 3) * 2;
#pragma unroll
    for (int t = 0; t < 8; t++) {
        const int c = h * HD + t * 8 + colb;
        const size_t i0 = ((size_t)b * Tdim + row0) * (NH * HD) + c;
        const size_t i1 = ((size_t)b * Tdim + row0 + 8) * (NH * HD) + c;
        float a0 = o[t][0] * inv0, a1 = o[t][1] * inv0;
        float a2 = o[t][2] * inv1, a3 = o[t][3] * inv1;
        *(uint32_t*)(g_oh + i0) = pack_hi(a0, a1);
        *(uint32_t*)(g_ol + i0) = pack_lo(a0, a1);
        *(uint32_t*)(g_oh + i1) = pack_hi(a2, a3);
        *(uint32_t*)(g_ol + i1) = pack_lo(a2, a3);
    }
}

// ---------------- launch ----------------------------------------------------
extern "C" void kernel_launch(void* const* d_in, const int* in_sizes, int n_in,
                              void* d_out, int out_size) {
    const float* hidden = (const float*)d_in[0];
    const float* cosp   = (const float*)d_in[1];
    const float* sinp   = (const float*)d_in[2];
    const float* wq     = (const float*)d_in[3];
    const float* wk     = (const float*)d_in[4];
    const float* wv     = (const float*)d_in[5];
    const float* wo     = (const float*)d_in[6];
    float* out = (float*)d_out;

    float *qt, *kt, *vt;
    ushort_t *hh, *hl, *wqh, *wql, *wkh, *wkl, *wvh, *wvl, *woh, *wol, *oh, *ol;
    cudaGetSymbolAddress((void**)&qt,  g_qt);
    cudaGetSymbolAddress((void**)&kt,  g_kt);
    cudaGetSymbolAddress((void**)&vt,  g_vt);
    cudaGetSymbolAddress((void**)&hh,  g_hh);
    cudaGetSymbolAddress((void**)&hl,  g_hl);
    cudaGetSymbolAddress((void**)&wqh, g_wqh);
    cudaGetSymbolAddress((void**)&wql, g_wql);
    cudaGetSymbolAddress((void**)&wkh, g_wkh);
    cudaGetSymbolAddress((void**)&wkl, g_wkl);
    cudaGetSymbolAddress((void**)&wvh, g_wvh);
    cudaGetSymbolAddress((void**)&wvl, g_wvl);
    cudaGetSymbolAddress((void**)&woh, g_woh);
    cudaGetSymbolAddress((void**)&wol, g_wol);
    cudaGetSymbolAddress((void**)&oh,  g_oh);
    cudaGetSymbolAddress((void**)&ol,  g_ol);

    cudaFuncSetAttribute(gemm_mma_s, cudaFuncAttributeMaxDynamicSharedMemorySize,
                         G_SMEM);
    cudaFuncSetAttribute(flash_mma, cudaFuncAttributeMaxDynamicSharedMemorySize,
                         FA_SMEM);

    // pre-split inputs (bf16 hi/lo)
    split_f32<<<(BT * HID / 4 + 255) / 256, 256>>>(hidden, hh, hl, BT * HID / 4);
    split_f32<<<(HID * HID / 4 + 255) / 256, 256>>>(wq, wqh, wql, HID * HID / 4);
    split_f32<<<(NKV * HD * HID / 4 + 255) / 256, 256>>>(wk, wkh, wkl, NKV * HD * HID / 4);
    split_f32<<<(NKV * HD * HID / 4 + 255) / 256, 256>>>(wv, wvh, wvl, NKV * HD * HID / 4);
    split_f32<<<(HID * HID / 4 + 255) / 256, 256>>>(wo, woh, wol, HID * HID / 4);

    // QKV projections
    gemm_mma_s<<<dim3(16, 32), 256, G_SMEM>>>(hh, hl, wqh, wql, qt, BT, NH * HD, HID);
    gemm_mma_s<<<dim3(4, 32),  256, G_SMEM>>>(hh, hl, wkh, wkl, kt, BT, NKV * HD, HID);
    gemm_mma_s<<<dim3(4, 32),  256, G_SMEM>>>(hh, hl, wvh, wvl, vt, BT, NKV * HD, HID);

    // RoPE + transpose + split
    rope_split<<<BT, 256>>>(cosp, sinp);

    // Flash attention (tensor cores, cp.async pipeline)
    flash_mma<<<dim3(Tdim / 128, Bdim * NH), 256, FA_SMEM>>>();

    // Output projection
    gemm_mma_s<<<dim3(16, 32), 256, G_SMEM>>>(oh, ol, woh, wol, out, BT, HID, HID);
}

// round 11
// speedup vs baseline: 1.0055x; 1.0055x over previous
#include <cuda_runtime.h>
#include <cstdint>
#include <math.h>

#define Bdim 2
#define Tdim 2048
#define HID 2048
#define NH 32
#define NKV 8
#define HD 64
#define BT (Bdim * Tdim)   // 4096

typedef unsigned short ushort_t;

// ---------------- scratch (device globals; no allocations allowed) ----------
__device__ float g_qt[(size_t)BT * NH * HD];
__device__ float g_kt[(size_t)BT * NKV * HD];
__device__ float g_vt[(size_t)BT * NKV * HD];
__device__ __align__(16) ushort_t g_hh[(size_t)BT * HID];
__device__ __align__(16) ushort_t g_hl[(size_t)BT * HID];
__device__ __align__(16) ushort_t g_wqh[(size_t)NH * HD * HID];
__device__ __align__(16) ushort_t g_wql[(size_t)NH * HD * HID];
__device__ __align__(16) ushort_t g_wkh[(size_t)NKV * HD * HID];
__device__ __align__(16) ushort_t g_wkl[(size_t)NKV * HD * HID];
__device__ __align__(16) ushort_t g_wvh[(size_t)NKV * HD * HID];
__device__ __align__(16) ushort_t g_wvl[(size_t)NKV * HD * HID];
__device__ __align__(16) ushort_t g_woh[(size_t)HID * NH * HD];
__device__ __align__(16) ushort_t g_wol[(size_t)HID * NH * HD];
__device__ __align__(16) ushort_t g_qh[(size_t)Bdim * NH  * Tdim * HD];
__device__ __align__(16) ushort_t g_ql[(size_t)Bdim * NH  * Tdim * HD];
__device__ __align__(16) ushort_t g_kh[(size_t)Bdim * NKV * Tdim * HD];
__device__ __align__(16) ushort_t g_kl[(size_t)Bdim * NKV * Tdim * HD];
__device__ __align__(16) ushort_t g_vh[(size_t)Bdim * NKV * Tdim * HD];
__device__ __align__(16) ushort_t g_vl[(size_t)Bdim * NKV * Tdim * HD];
__device__ __align__(16) ushort_t g_oh[(size_t)BT * NH * HD];
__device__ __align__(16) ushort_t g_ol[(size_t)BT * NH * HD];

// ======================= helpers ============================================
static __device__ __forceinline__ uint32_t smem_u32(const void* p) {
    uint32_t a;
    asm("{ .reg .u64 t; cvta.to.shared.u64 t, %1; cvt.u32.u64 %0, t; }"
        : "=r"(a) : "l"(p));
    return a;
}

static __device__ __forceinline__ void ldm4(uint32_t* r, uint32_t addr) {
    asm volatile("ldmatrix.sync.aligned.m8n8.x4.shared.b16 {%0,%1,%2,%3}, [%4];"
                 : "=r"(r[0]), "=r"(r[1]), "=r"(r[2]), "=r"(r[3]) : "r"(addr));
}

static __device__ __forceinline__ void ldm4t(uint32_t* r, uint32_t addr) {
    asm volatile("ldmatrix.sync.aligned.m8n8.x4.trans.shared.b16 {%0,%1,%2,%3}, [%4];"
                 : "=r"(r[0]), "=r"(r[1]), "=r"(r[2]), "=r"(r[3]) : "r"(addr));
}

static __device__ __forceinline__ void mma16816(float* c, const uint32_t* a,
                                                uint32_t b0, uint32_t b1) {
    asm volatile("mma.sync.aligned.m16n8k16.row.col.f32.bf16.bf16.f32 "
                 "{%0,%1,%2,%3}, {%4,%5,%6,%7}, {%8,%9}, {%0,%1,%2,%3};"
                 : "+f"(c[0]), "+f"(c[1]), "+f"(c[2]), "+f"(c[3])
                 : "r"(a[0]), "r"(a[1]), "r"(a[2]), "r"(a[3]), "r"(b0), "r"(b1));
}

static __device__ __forceinline__ uint32_t pack_hi(float a, float b) {
    return __byte_perm(__float_as_uint(a), __float_as_uint(b), 0x7632);
}
static __device__ __forceinline__ uint32_t pack_lo(float a, float b) {
    float ra = a - __uint_as_float(__float_as_uint(a) & 0xFFFF0000u);
    float rb = b - __uint_as_float(__float_as_uint(b) & 0xFFFF0000u);
    uint32_t r;
    asm("cvt.rn.satfinite.bf16x2.f32 %0, %1, %2;" : "=r"(r) : "f"(rb), "f"(ra));
    return r;
}

static __device__ __forceinline__ float ex2(float x) {
    float r;
    asm("ex2.approx.f32 %0, %1;" : "=f"(r) : "f"(x));
    return r;
}

static __device__ __forceinline__ void split_store(float x, ushort_t* ph,
                                                   ushort_t* pl) {
    uint32_t u = __float_as_uint(x);
    *ph = (ushort_t)(u >> 16);
    float lo = x - __uint_as_float(u & 0xFFFF0000u);
    ushort_t ls;
    asm("cvt.rn.satfinite.bf16.f32 %0, %1;" : "=h"(ls) : "f"(lo));
    *pl = ls;
}

#define CP_ASYNC(dst, src) \
    asm volatile("cp.async.cg.shared.global [%0], [%1], 16;" \
                 :: "r"(dst), "l"(src) : "memory")
#define CP_COMMIT() asm volatile("cp.async.commit_group;" ::: "memory")
#define CP_WAIT1() asm volatile("cp.async.wait_group 1;" ::: "memory")
#define CP_WAIT0() asm volatile("cp.async.wait_group 0;" ::: "memory")

// ---------------- input pre-split ------------------------------------------
__global__ __launch_bounds__(256) void split_f32(const float* __restrict__ src,
                                                 ushort_t* __restrict__ hi,
                                                 ushort_t* __restrict__ lo,
                                                 int n4) {
    int i = blockIdx.x * blockDim.x + threadIdx.x;
    if (i < n4) {
        float4 f = ((const float4*)src)[i];
        ((uint2*)hi)[i] = make_uint2(pack_hi(f.x, f.y), pack_hi(f.z, f.w));
        ((uint2*)lo)[i] = make_uint2(pack_lo(f.x, f.y), pack_lo(f.z, f.w));
    }
}

// =============== mma.sync GEMM (pre-split inputs, cp.async pipeline) ========
#define G_ROWB 80
#define G_TILE 10240
#define G_STAGE_B (4 * G_TILE)
#define G_SMEM (2 * G_STAGE_B + 128)

__global__ __launch_bounds__(256, 2) void gemm_mma_s(
    const ushort_t* __restrict__ Ah, const ushort_t* __restrict__ Al,
    const ushort_t* __restrict__ Bh, const ushort_t* __restrict__ Bl,
    float* __restrict__ C, int M, int N, int K) {
    extern __shared__ char dsm[];
    const uint32_t tile = (smem_u32(dsm) + 127u) & ~127u;

    const int tid = threadIdx.x;
    const int wid = tid >> 5;
    const int lane = tid & 31;
    const int wm = wid & 3;
    const int wn = wid >> 2;
    const int bm = blockIdx.y * 128;
    const int bn = blockIdx.x * 128;

    const int row = tid >> 1;
    const int half = tid & 1;
    const ushort_t* pAh = Ah + (size_t)(bm + row) * K + half * 16;
    const ushort_t* pAl = Al + (size_t)(bm + row) * K + half * 16;
    const ushort_t* pBh = Bh + (size_t)(bn + row) * K + half * 16;
    const ushort_t* pBl = Bl + (size_t)(bn + row) * K + half * 16;
    const uint32_t s_row = (uint32_t)(row * G_ROWB + half * 32);

    const int r8 = lane & 7, sub = lane >> 3;
    const uint32_t a_off = (uint32_t)((wm * 32 + r8 + (sub & 1) * 8) * G_ROWB +
                                      (sub >> 1) * 16);
    const uint32_t b_off = (uint32_t)((wn * 64 + r8 + (sub >> 1) * 8) * G_ROWB +
                                      (sub & 1) * 16);

    float acc[2][8][4];
#pragma unroll
    for (int i = 0; i < 2; i++)
#pragma unroll
        for (int j = 0; j < 8; j++)
#pragma unroll
            for (int q = 0; q < 4; q++) acc[i][j][q] = 0.f;

    const int nch = K >> 5;

#define G_ISSUE(chunk, sb) do {                                               \
    const int _k0 = (chunk) << 5;                                             \
    CP_ASYNC((sb) + s_row,                   pAh + _k0);                      \
    CP_ASYNC((sb) + s_row + 16,              pAh + _k0 + 8);                  \
    CP_ASYNC((sb) + G_TILE + s_row,          pAl + _k0);                      \
    CP_ASYNC((sb) + G_TILE + s_row + 16,     pAl + _k0 + 8);                  \
    CP_ASYNC((sb) + 2 * G_TILE + s_row,      pBh + _k0);                      \
    CP_ASYNC((sb) + 2 * G_TILE + s_row + 16, pBh + _k0 + 8);                  \
    CP_ASYNC((sb) + 3 * G_TILE + s_row,      pBl + _k0);                      \
    CP_ASYNC((sb) + 3 * G_TILE + s_row + 16, pBl + _k0 + 8);                  \
} while (0)

    G_ISSUE(0, tile);              CP_COMMIT();
    G_ISSUE(1, tile + G_STAGE_B);  CP_COMMIT();

    for (int i = 0; i < nch; i++) {
        const uint32_t cur = tile + (uint32_t)(i & 1) * G_STAGE_B;
        if (i + 1 < nch) { CP_WAIT1(); } else { CP_WAIT0(); }
        __syncthreads();

#pragma unroll
        for (int ks = 0; ks < 2; ks++) {
            uint32_t ah[8], al[8];
            const uint32_t ka = cur + a_off + ks * 32;
            ldm4(ah,     ka);
            ldm4(ah + 4, ka + 16 * G_ROWB);
            ldm4(al,     ka + G_TILE);
            ldm4(al + 4, ka + G_TILE + 16 * G_ROWB);
#pragma unroll
            for (int g = 0; g < 4; g++) {
                uint32_t bh[4], bl[4];
                const uint32_t kb = cur + 2 * G_TILE + b_off + ks * 32 +
                                    g * (16 * G_ROWB);
                ldm4(bh, kb);
                ldm4(bl, kb + G_TILE);
#pragma unroll
                for (int ms = 0; ms < 2; ms++) {
                    mma16816(acc[ms][2 * g],     ah + 4 * ms, bh[0], bh[1]);
                    mma16816(acc[ms][2 * g + 1], ah + 4 * ms, bh[2], bh[3]);
                    mma16816(acc[ms][2 * g],     ah + 4 * ms, bl[0], bl[1]);
                    mma16816(acc[ms][2 * g + 1], ah + 4 * ms, bl[2], bl[3]);
                    mma16816(acc[ms][2 * g],     al + 4 * ms, bh[0], bh[1]);
                    mma16816(acc[ms][2 * g + 1], al + 4 * ms, bh[2], bh[3]);
                }
            }
        }
        __syncthreads();
        if (i + 2 < nch) {
            G_ISSUE(i + 2, cur);
            CP_COMMIT();
        }
    }
#undef G_ISSUE

    const int trow = lane >> 2;
    const int tcol = (lane & 3) * 2;
#pragma unroll
    for (int ms = 0; ms < 2; ms++) {
#pragma unroll
        for (int nf = 0; nf < 8; nf++) {
            const int r = bm + wm * 32 + ms * 16 + trow;
            const int c = bn + wn * 64 + nf * 8 + tcol;
            *(float2*)(C + (size_t)r * N + c) =
                make_float2(acc[ms][nf][0], acc[ms][nf][1]);
            *(float2*)(C + (size_t)(r + 8) * N + c) =
                make_float2(acc[ms][nf][2], acc[ms][nf][3]);
        }
    }
}

// ---------------- RoPE + head transpose + bf16 split ------------------------
__global__ __launch_bounds__(256) void rope_split(const float* __restrict__ cosp,
                                                  const float* __restrict__ sinp) {
    const int token = blockIdx.x;
    const int b = token / Tdim;
    const int t = token % Tdim;
    __shared__ float cs[HD], sn[HD];
    if (threadIdx.x < HD) {
        cs[threadIdx.x] = cosp[(size_t)token * HD + threadIdx.x];
        sn[threadIdx.x] = sinp[(size_t)token * HD + threadIdx.x];
    }
    __syncthreads();

    const float qsc = 0.125f * 1.4426950408889634f;
    for (int p = threadIdx.x; p < NH * 32; p += 256) {
        const int hh = p >> 5;
        const int d  = p & 31;
        const size_t src = (size_t)token * (NH * HD) + hh * HD + d;
        float x1 = g_qt[src];
        float x2 = g_qt[src + 32];
        float c = cs[d], s = sn[d];
        const size_t base = ((size_t)(b * NH + hh) * Tdim + t) * HD;
        float y1 = (x1 * c - x2 * s) * qsc;
        float y2 = (x2 * c + x1 * s) * qsc;
        split_store(y1, &g_qh[base + d],      &g_ql[base + d]);
        split_store(y2, &g_qh[base + d + 32], &g_ql[base + d + 32]);
    }
    for (int p = threadIdx.x; p < NKV * 32; p += 256) {
        const int hh = p >> 5;
        const int d  = p & 31;
        const size_t src = (size_t)token * (NKV * HD) + hh * HD + d;
        float x1 = g_kt[src];
        float x2 = g_kt[src + 32];
        float c = cs[d], s = sn[d];
        const size_t base = ((size_t)(b * NKV + hh) * Tdim + t) * HD;
        float y1 = x1 * c - x2 * s;
        float y2 = x2 * c + x1 * s;
        split_store(y1, &g_kh[base + d],      &g_kl[base + d]);
        split_store(y2, &g_kh[base + d + 32], &g_kl[base + d + 32]);
    }
    for (int e = threadIdx.x; e < NKV * HD; e += 256) {
        const int hh = e >> 6;
        const int d  = e & 63;
        float v = g_vt[(size_t)token * (NKV * HD) + e];
        const size_t base = ((size_t)(b * NKV + hh) * Tdim + t) * HD;
        split_store(v, &g_vh[base + d], &g_vl[base + d]);
    }
}

// ---------------- Flash attention (tensor cores, cp.async K/V pipeline) -----
// Br=128, Bc=64, 256 threads (8 warps). Q resident; K/V double-buffered.
// P repack fused into PV loop to keep live registers under the 128 cap.
#define FB 144
#define FA_STAGE_B 36864
#define FA_SMEM (36864 + 2 * FA_STAGE_B)   // 110592

__global__ __launch_bounds__(256, 2) void flash_mma() {
    extern __shared__ ushort_t fsm[];
    const uint32_t s0 = smem_u32(fsm);
    const uint32_t sQh = s0, sQl = s0 + 18432;

    const int tid = threadIdx.x;
    const int lane = tid & 31;
    const int w = tid >> 5;
    const int qtile = (int)gridDim.x - 1 - (int)blockIdx.x;  // big first
    const int bh = blockIdx.y;
    const int b = bh / NH;
    const int h = bh % NH;
    const int kvh = h / (NH / NKV);

    const ushort_t* qhp = g_qh + ((size_t)bh * Tdim + qtile * 128) * HD;
    const ushort_t* qlp = g_ql + ((size_t)bh * Tdim + qtile * 128) * HD;
    const size_t kvbase = (size_t)(b * NKV + kvh) * Tdim * HD;
    const ushort_t* pkh = g_kh + kvbase;
    const ushort_t* pkl = g_kl + kvbase;
    const ushort_t* pvh = g_vh + kvbase;
    const ushort_t* pvl = g_vl + kvbase;

    const uint32_t d0 = (uint32_t)((tid >> 3) * FB + (tid & 7) * 16);
    const uint32_t d1 = (uint32_t)(((tid + 256) >> 3) * FB + (tid & 7) * 16);
    const uint32_t g0 = (uint32_t)((tid >> 3) * HD + (tid & 7) * 8);
    const uint32_t g1 = (uint32_t)(((tid + 256) >> 3) * HD + (tid & 7) * 8);

#define FA_ISSUE(kt, stg) do {                                                \
    const uint32_t _sb = s0 + 36864 + (uint32_t)(stg) * FA_STAGE_B;           \
    const size_t _go = (size_t)(kt) * 64 * HD;                                \
    CP_ASYNC(_sb + d0,         pkh + _go + g0);                               \
    CP_ASYNC(_sb + d1,         pkh + _go + g1);                               \
    CP_ASYNC(_sb + 9216 + d0,  pkl + _go + g0);                               \
    CP_ASYNC(_sb + 9216 + d1,  pkl + _go + g1);                               \
    CP_ASYNC(_sb + 18432 + d0, pvh + _go + g0);                               \
    CP_ASYNC(_sb + 18432 + d1, pvh + _go + g1);                               \
    CP_ASYNC(_sb + 27648 + d0, pvl + _go + g0);                               \
    CP_ASYNC(_sb + 27648 + d1, pvl + _go + g1);                               \
} while (0)

    FA_ISSUE(0, 0); CP_COMMIT();
    FA_ISSUE(1, 1); CP_COMMIT();

    // stage Q (128x64 bf16 x2)
#pragma unroll
    for (int j = 0; j < 4; j++) {
        const int idx = tid + j * 256;
        const int qr = idx >> 3;
        const int qc = idx & 7;
        *(uint4*)(fsm + qr * 72 + qc * 8)        = *(const uint4*)(qhp + qr * HD + qc * 8);
        *(uint4*)(fsm + 9216 + qr * 72 + qc * 8) = *(const uint4*)(qlp + qr * HD + qc * 8);
    }

    const int r8 = lane & 7, sub = lane >> 3;
    const uint32_t a_off = (uint32_t)((w * 16 + r8 + ((sub & 1) << 3)) * FB +
                                      ((sub >> 1) << 4));
    const uint32_t b_off = (uint32_t)((r8 + ((sub >> 1) << 3)) * FB +
                                      ((sub & 1) << 4));
    const uint32_t v_off = (uint32_t)(((lane & 8) + (lane & 7)) * FB +
                                      (lane >> 4) * 16);

    float m0 = -1e30f, m1 = -1e30f, l0 = 0.f, l1 = 0.f;
    float o[8][4];
#pragma unroll
    for (int t = 0; t < 8; t++)
#pragma unroll
        for (int e = 0; e < 4; e++) o[t][e] = 0.f;

    const int ktmax = 2 * qtile + 1;
    for (int kt = 0; kt <= ktmax; kt++) {
        const uint32_t stg = s0 + 36864 + (uint32_t)(kt & 1) * FA_STAGE_B;
        if (kt < ktmax) { CP_WAIT1(); } else { CP_WAIT0(); }
        __syncthreads();

        // --- S = Q K^T (3x split, base-2 logits) ---
        float sa[8][4];
#pragma unroll
        for (int t = 0; t < 8; t++)
#pragma unroll
            for (int e = 0; e < 4; e++) sa[t][e] = 0.f;

#pragma unroll
        for (int ks = 0; ks < 4; ks++) {
            uint32_t aqh[4], aql[4];
            ldm4(aqh, sQh + a_off + ks * 32);
            ldm4(aql, sQl + a_off + ks * 32);
#pragma unroll
            for (int g = 0; g < 4; g++) {
                uint32_t kbh[4], kbl[4];
                const uint32_t kb = stg + b_off + ks * 32 + g * (16 * FB);
                ldm4(kbh, kb);
                ldm4(kbl, kb + 9216);
                mma16816(sa[2 * g],     aqh, kbh[0], kbh[1]);
                mma16816(sa[2 * g + 1], aqh, kbh[2], kbh[3]);
                mma16816(sa[2 * g],     aqh, kbl[0], kbl[1]);
                mma16816(sa[2 * g + 1], aqh, kbl[2], kbl[3]);
                mma16816(sa[2 * g],     aql, kbh[0], kbh[1]);
                mma16816(sa[2 * g + 1], aql, kbh[2], kbh[3]);
            }
        }

        // --- causal mask (last two tiles only) ---
        if (kt >= 2 * qtile) {
            const int row0 = qtile * 128 + w * 16 + (lane >> 2);
            const int cb = kt * 64 + (lane & 3) * 2;
#pragma unroll
            for (int t = 0; t < 8; t++) {
                const int c0 = cb + t * 8;
                if (c0 > row0)         sa[t][0] = -1e30f;
                if (c0 + 1 > row0)     sa[t][1] = -1e30f;
                if (c0 > row0 + 8)     sa[t][2] = -1e30f;
                if (c0 + 1 > row0 + 8) sa[t][3] = -1e30f;
            }
        }

        // --- online softmax (base 2) ---
        float rm0 = -1e30f, rm1 = -1e30f;
#pragma unroll
        for (int t = 0; t < 8; t++) {
            rm0 = fmaxf(rm0, fmaxf(sa[t][0], sa[t][1]));
            rm1 = fmaxf(rm1, fmaxf(sa[t][2], sa[t][3]));
        }
        rm0 = fmaxf(rm0, __shfl_xor_sync(0xffffffffu, rm0, 1));
        rm0 = fmaxf(rm0, __shfl_xor_sync(0xffffffffu, rm0, 2));
        rm1 = fmaxf(rm1, __shfl_xor_sync(0xffffffffu, rm1, 1));
        rm1 = fmaxf(rm1, __shfl_xor_sync(0xffffffffu, rm1, 2));
        const float mn0 = fmaxf(m0, rm0);
        const float mn1 = fmaxf(m1, rm1);
        const float al0 = ex2(m0 - mn0);
        const float al1 = ex2(m1 - mn1);
        m0 = mn0; m1 = mn1;
        float rs0 = 0.f, rs1 = 0.f;
#pragma unroll
        for (int t = 0; t < 8; t++) {
            sa[t][0] = ex2(sa[t][0] - mn0);
            sa[t][1] = ex2(sa[t][1] - mn0);
            sa[t][2] = ex2(sa[t][2] - mn1);
            sa[t][3] = ex2(sa[t][3] - mn1);
            rs0 += sa[t][0] + sa[t][1];
            rs1 += sa[t][2] + sa[t][3];
        }
        rs0 += __shfl_xor_sync(0xffffffffu, rs0, 1);
        rs0 += __shfl_xor_sync(0xffffffffu, rs0, 2);
        rs1 += __shfl_xor_sync(0xffffffffu, rs1, 1);
        rs1 += __shfl_xor_sync(0xffffffffu, rs1, 2);
        l0 = l0 * al0 + rs0;
        l1 = l1 * al1 + rs1;
#pragma unroll
        for (int t = 0; t < 8; t++) {
            o[t][0] *= al0; o[t][1] *= al0;
            o[t][2] *= al1; o[t][3] *= al1;
        }

        // --- O += P V (3x split); P packed per-kc to cap live registers ---
        const uint32_t sVh = stg + 18432;
#pragma unroll
        for (int kc = 0; kc < 4; kc++) {
            const int t0 = 2 * kc, t1 = 2 * kc + 1;
            uint32_t aph[4], apl[4];
            aph[0] = pack_hi(sa[t0][0], sa[t0][1]);
            aph[1] = pack_hi(sa[t0][2], sa[t0][3]);
            aph[2] = pack_hi(sa[t1][0], sa[t1][1]);
            aph[3] = pack_hi(sa[t1][2], sa[t1][3]);
            apl[0] = pack_lo(sa[t0][0], sa[t0][1]);
            apl[1] = pack_lo(sa[t0][2], sa[t0][3]);
            apl[2] = pack_lo(sa[t1][0], sa[t1][1]);
            apl[3] = pack_lo(sa[t1][2], sa[t1][3]);
#pragma unroll
            for (int tp = 0; tp < 4; tp++) {
                uint32_t vbh[4], vbl[4];
                const uint32_t va = sVh + v_off + kc * (16 * FB) + tp * 32;
                ldm4t(vbh, va);
                ldm4t(vbl, va + 9216);
                mma16816(o[2 * tp],     aph, vbh[0], vbh[1]);
                mma16816(o[2 * tp + 1], aph, vbh[2], vbh[3]);
                mma16816(o[2 * tp],     aph, vbl[0], vbl[1]);
                mma16816(o[2 * tp + 1], aph, vbl[2], vbl[3]);
                mma16816(o[2 * tp],     apl, vbh[0], vbh[1]);
                mma16816(o[2 * tp + 1], apl, vbh[2], vbh[3]);
            }
        }

        __syncthreads();
        if (kt + 2 <= ktmax) {
            FA_ISSUE(kt + 2, kt & 1);
            CP_COMMIT();
        }
    }
#undef FA_ISSUE

    // epilogue: normalize + split-write for the O projection
    const float inv0 = 1.0f / l0;
    const float inv1 = 1.0f / l1;
    const int row0 = qtile * 128 + w * 16 + (lane >> 2);
    const int colb = (lane & 3) * 2;
#pragma unroll
    for (int t = 0; t < 8; t++) {
        const int c = h * HD + t * 8 + colb;
        const size_t i0 = ((size_t)b * Tdim + row0) * (NH * HD) + c;
        const size_t i1 = ((size_t)b * Tdim + row0 + 8) * (NH * HD) + c;
        float a0 = o[t][0] * inv0, a1 = o[t][1] * inv0;
        float a2 = o[t][2] * inv1, a3 = o[t][3] * inv1;
        *(uint32_t*)(g_oh + i0) = pack_hi(a0, a1);
        *(uint32_t*)(g_ol + i0) = pack_lo(a0, a1);
        *(uint32_t*)(g_oh + i1) = pack_hi(a2, a3);
        *(uint32_t*)(g_ol + i1) = pack_lo(a2, a3);
    }
}

// ---------------- launch ----------------------------------------------------
extern "C" void kernel_launch(void* const* d_in, const int* in_sizes, int n_in,
                              void* d_out, int out_size) {
    const float* hidden = (const float*)d_in[0];
    const float* cosp   = (const float*)d_in[1];
    const float* sinp   = (const float*)d_in[2];
    const float* wq     = (const float*)d_in[3];
    const float* wk     = (const float*)d_in[4];
    const float* wv     = (const float*)d_in[5];
    const float* wo     = (const float*)d_in[6];
    float* out = (float*)d_out;

    float *qt, *kt, *vt;
    ushort_t *hh, *hl, *wqh, *wql, *wkh, *wkl, *wvh, *wvl, *woh, *wol, *oh, *ol;
    cudaGetSymbolAddress((void**)&qt,  g_qt);
    cudaGetSymbolAddress((void**)&kt,  g_kt);
    cudaGetSymbolAddress((void**)&vt,  g_vt);
    cudaGetSymbolAddress((void**)&hh,  g_hh);
    cudaGetSymbolAddress((void**)&hl,  g_hl);
    cudaGetSymbolAddress((void**)&wqh, g_wqh);
    cudaGetSymbolAddress((void**)&wql, g_wql);
    cudaGetSymbolAddress((void**)&wkh, g_wkh);
    cudaGetSymbolAddress((void**)&wkl, g_wkl);
    cudaGetSymbolAddress((void**)&wvh, g_wvh);
    cudaGetSymbolAddress((void**)&wvl, g_wvl);
    cudaGetSymbolAddress((void**)&woh, g_woh);
    cudaGetSymbolAddress((void**)&wol, g_wol);
    cudaGetSymbolAddress((void**)&oh,  g_oh);
    cudaGetSymbolAddress((void**)&ol,  g_ol);

    cudaFuncSetAttribute(gemm_mma_s, cudaFuncAttributeMaxDynamicSharedMemorySize,
                         G_SMEM);
    cudaFuncSetAttribute(flash_mma, cudaFuncAttributeMaxDynamicSharedMemorySize,
                         FA_SMEM);

    // pre-split inputs (bf16 hi/lo)
    split_f32<<<(BT * HID / 4 + 255) / 256, 256>>>(hidden, hh, hl, BT * HID / 4);
    split_f32<<<(HID * HID / 4 + 255) / 256, 256>>>(wq, wqh, wql, HID * HID / 4);
    split_f32<<<(NKV * HD * HID / 4 + 255) / 256, 256>>>(wk, wkh, wkl, NKV * HD * HID / 4);
    split_f32<<<(NKV * HD * HID / 4 + 255) / 256, 256>>>(wv, wvh, wvl, NKV * HD * HID / 4);
    split_f32<<<(HID * HID / 4 + 255) / 256, 256>>>(wo, woh, wol, HID * HID / 4);

    // QKV projections
    gemm_mma_s<<<dim3(16, 32), 256, G_SMEM>>>(hh, hl, wqh, wql, qt, BT, NH * HD, HID);
    gemm_mma_s<<<dim3(4, 32),  256, G_SMEM>>>(hh, hl, wkh, wkl, kt, BT, NKV * HD, HID);
    gemm_mma_s<<<dim3(4, 32),  256, G_SMEM>>>(hh, hl, wvh, wvl, vt, BT, NKV * HD, HID);

    // RoPE + transpose + split
    rope_split<<<BT, 256>>>(cosp, sinp);

    // Flash attention (tensor cores, cp.async pipeline, reduced reg pressure)
    flash_mma<<<dim3(Tdim / 128, Bdim * NH), 256, FA_SMEM>>>();

    // Output projection
    gemm_mma_s<<<dim3(16, 32), 256, G_SMEM>>>(oh, ol, woh, wol, out, BT, HID, HID);
}

// round 12
// speedup vs baseline: 1.0319x; 1.0263x over previous
#include <cuda_runtime.h>
#include <cstdint>
#include <math.h>

#define Bdim 2
#define Tdim 2048
#define HID 2048
#define NH 32
#define NKV 8
#define HD 64
#define BT (Bdim * Tdim)   // 4096

typedef unsigned short ushort_t;

// ---------------- scratch (device globals; no allocations allowed) ----------
__device__ __align__(16) ushort_t g_hh[(size_t)BT * HID];
__device__ __align__(16) ushort_t g_hl[(size_t)BT * HID];
__device__ __align__(16) ushort_t g_wqh[(size_t)NH * HD * HID];
__device__ __align__(16) ushort_t g_wql[(size_t)NH * HD * HID];
__device__ __align__(16) ushort_t g_wkh[(size_t)NKV * HD * HID];
__device__ __align__(16) ushort_t g_wkl[(size_t)NKV * HD * HID];
__device__ __align__(16) ushort_t g_wvh[(size_t)NKV * HD * HID];
__device__ __align__(16) ushort_t g_wvl[(size_t)NKV * HD * HID];
__device__ __align__(16) ushort_t g_woh[(size_t)HID * NH * HD];
__device__ __align__(16) ushort_t g_wol[(size_t)HID * NH * HD];
__device__ __align__(16) ushort_t g_qh[(size_t)Bdim * NH  * Tdim * HD];
__device__ __align__(16) ushort_t g_ql[(size_t)Bdim * NH  * Tdim * HD];
__device__ __align__(16) ushort_t g_kh[(size_t)Bdim * NKV * Tdim * HD];
__device__ __align__(16) ushort_t g_kl[(size_t)Bdim * NKV * Tdim * HD];
__device__ __align__(16) ushort_t g_vh[(size_t)Bdim * NKV * Tdim * HD];
__device__ __align__(16) ushort_t g_vl[(size_t)Bdim * NKV * Tdim * HD];
__device__ __align__(16) ushort_t g_oh[(size_t)BT * NH * HD];
__device__ __align__(16) ushort_t g_ol[(size_t)BT * NH * HD];

// ======================= helpers ============================================
static __device__ __forceinline__ uint32_t smem_u32(const void* p) {
    uint32_t a;
    asm("{ .reg .u64 t; cvta.to.shared.u64 t, %1; cvt.u32.u64 %0, t; }"
        : "=r"(a) : "l"(p));
    return a;
}

static __device__ __forceinline__ void ldm4(uint32_t* r, uint32_t addr) {
    asm volatile("ldmatrix.sync.aligned.m8n8.x4.shared.b16 {%0,%1,%2,%3}, [%4];"
                 : "=r"(r[0]), "=r"(r[1]), "=r"(r[2]), "=r"(r[3]) : "r"(addr));
}

static __device__ __forceinline__ void ldm4t(uint32_t* r, uint32_t addr) {
    asm volatile("ldmatrix.sync.aligned.m8n8.x4.trans.shared.b16 {%0,%1,%2,%3}, [%4];"
                 : "=r"(r[0]), "=r"(r[1]), "=r"(r[2]), "=r"(r[3]) : "r"(addr));
}

static __device__ __forceinline__ void mma16816(float* c, const uint32_t* a,
                                                uint32_t b0, uint32_t b1) {
    asm volatile("mma.sync.aligned.m16n8k16.row.col.f32.bf16.bf16.f32 "
                 "{%0,%1,%2,%3}, {%4,%5,%6,%7}, {%8,%9}, {%0,%1,%2,%3};"
                 : "+f"(c[0]), "+f"(c[1]), "+f"(c[2]), "+f"(c[3])
                 : "r"(a[0]), "r"(a[1]), "r"(a[2]), "r"(a[3]), "r"(b0), "r"(b1));
}

static __device__ __forceinline__ uint32_t pack_hi(float a, float b) {
    return __byte_perm(__float_as_uint(a), __float_as_uint(b), 0x7632);
}
static __device__ __forceinline__ uint32_t pack_lo(float a, float b) {
    float ra = a - __uint_as_float(__float_as_uint(a) & 0xFFFF0000u);
    float rb = b - __uint_as_float(__float_as_uint(b) & 0xFFFF0000u);
    uint32_t r;
    asm("cvt.rn.satfinite.bf16x2.f32 %0, %1, %2;" : "=r"(r) : "f"(rb), "f"(ra));
    return r;
}

static __device__ __forceinline__ float ex2(float x) {
    float r;
    asm("ex2.approx.f32 %0, %1;" : "=f"(r) : "f"(x));
    return r;
}

static __device__ __forceinline__ void split_store(float x, ushort_t* ph,
                                                   ushort_t* pl) {
    uint32_t u = __float_as_uint(x);
    *ph = (ushort_t)(u >> 16);
    float lo = x - __uint_as_float(u & 0xFFFF0000u);
    ushort_t ls;
    asm("cvt.rn.satfinite.bf16.f32 %0, %1;" : "=h"(ls) : "f"(lo));
    *pl = ls;
}

#define CP_ASYNC(dst, src) \
    asm volatile("cp.async.cg.shared.global [%0], [%1], 16;" \
                 :: "r"(dst), "l"(src) : "memory")
#define CP_COMMIT() asm volatile("cp.async.commit_group;" ::: "memory")
#define CP_WAIT1() asm volatile("cp.async.wait_group 1;" ::: "memory")
#define CP_WAIT0() asm volatile("cp.async.wait_group 0;" ::: "memory")

// ---------------- input pre-split ------------------------------------------
__global__ __launch_bounds__(256) void split_f32(const float* __restrict__ src,
                                                 ushort_t* __restrict__ hi,
                                                 ushort_t* __restrict__ lo,
                                                 int n4) {
    int i = blockIdx.x * blockDim.x + threadIdx.x;
    if (i < n4) {
        float4 f = ((const float4*)src)[i];
        ((uint2*)hi)[i] = make_uint2(pack_hi(f.x, f.y), pack_hi(f.z, f.w));
        ((uint2*)lo)[i] = make_uint2(pack_lo(f.x, f.y), pack_lo(f.z, f.w));
    }
}

// =============== mma.sync GEMM with fused epilogues =========================
// C[M,N] = (Ah+Al)[M,K] * (Bh+Bl)[N,K]^T, 3-term split, fp32 accum.
// MODE 0: store fp32 C. MODE 1: rope+scale+split -> g_qh/g_ql.
// MODE 2: blockIdx.x<4 -> K rope+split -> g_kh/g_kl; else V split -> g_vh/g_vl.
#define G_ROWB 80
#define G_TILE 10240
#define G_STAGE_B (4 * G_TILE)
#define G_SMEM (2 * G_STAGE_B + 128)

template<int MODE>
__global__ __launch_bounds__(256, 2) void gemm_fused(
    const ushort_t* __restrict__ Ah, const ushort_t* __restrict__ Al,
    const ushort_t* __restrict__ Bh1, const ushort_t* __restrict__ Bl1,
    const ushort_t* __restrict__ Bh2, const ushort_t* __restrict__ Bl2,
    float* __restrict__ C,
    const float* __restrict__ cosp, const float* __restrict__ sinp,
    int N, int K) {
    extern __shared__ char dsm[];
    const uint32_t tile = (smem_u32(dsm) + 127u) & ~127u;

    const int tid = threadIdx.x;
    const int wid = tid >> 5;
    const int lane = tid & 31;
    const int wm = wid & 3;
    const int wn = wid >> 2;
    const bool isV = (MODE == 2) && (blockIdx.x >= 4);
    const int bnx = isV ? ((int)blockIdx.x - 4) : (int)blockIdx.x;
    const int bm = blockIdx.y * 128;
    const int bn = bnx * 128;
    const ushort_t* Bh = isV ? Bh2 : Bh1;
    const ushort_t* Bl = isV ? Bl2 : Bl1;

    const int row = tid >> 1;
    const int half = tid & 1;
    const ushort_t* pAh = Ah + (size_t)(bm + row) * K + half * 16;
    const ushort_t* pAl = Al + (size_t)(bm + row) * K + half * 16;
    const ushort_t* pBh = Bh + (size_t)(bn + row) * K + half * 16;
    const ushort_t* pBl = Bl + (size_t)(bn + row) * K + half * 16;
    const uint32_t s_row = (uint32_t)(row * G_ROWB + half * 32);

    const int r8 = lane & 7, sub = lane >> 3;
    const uint32_t a_off = (uint32_t)((wm * 32 + r8 + (sub & 1) * 8) * G_ROWB +
                                      (sub >> 1) * 16);
    const uint32_t b_off = (uint32_t)((wn * 64 + r8 + (sub >> 1) * 8) * G_ROWB +
                                      (sub & 1) * 16);

    float acc[2][8][4];
#pragma unroll
    for (int i = 0; i < 2; i++)
#pragma unroll
        for (int j = 0; j < 8; j++)
#pragma unroll
            for (int q = 0; q < 4; q++) acc[i][j][q] = 0.f;

    const int nch = K >> 5;

#define G_ISSUE(chunk, sb) do {                                               \
    const int _k0 = (chunk) << 5;                                             \
    CP_ASYNC((sb) + s_row,                   pAh + _k0);                      \
    CP_ASYNC((sb) + s_row + 16,              pAh + _k0 + 8);                  \
    CP_ASYNC((sb) + G_TILE + s_row,          pAl + _k0);                      \
    CP_ASYNC((sb) + G_TILE + s_row + 16,     pAl + _k0 + 8);                  \
    CP_ASYNC((sb) + 2 * G_TILE + s_row,      pBh + _k0);                      \
    CP_ASYNC((sb) + 2 * G_TILE + s_row + 16, pBh + _k0 + 8);                  \
    CP_ASYNC((sb) + 3 * G_TILE + s_row,      pBl + _k0);                      \
    CP_ASYNC((sb) + 3 * G_TILE + s_row + 16, pBl + _k0 + 8);                  \
} while (0)

    G_ISSUE(0, tile);              CP_COMMIT();
    G_ISSUE(1, tile + G_STAGE_B);  CP_COMMIT();

    for (int i = 0; i < nch; i++) {
        const uint32_t cur = tile + (uint32_t)(i & 1) * G_STAGE_B;
        if (i + 1 < nch) { CP_WAIT1(); } else { CP_WAIT0(); }
        __syncthreads();

#pragma unroll
        for (int ks = 0; ks < 2; ks++) {
            uint32_t ah[8], al[8];
            const uint32_t ka = cur + a_off + ks * 32;
            ldm4(ah,     ka);
            ldm4(ah + 4, ka + 16 * G_ROWB);
            ldm4(al,     ka + G_TILE);
            ldm4(al + 4, ka + G_TILE + 16 * G_ROWB);
#pragma unroll
            for (int g = 0; g < 4; g++) {
                uint32_t bh[4], bl[4];
                const uint32_t kb = cur + 2 * G_TILE + b_off + ks * 32 +
                                    g * (16 * G_ROWB);
                ldm4(bh, kb);
                ldm4(bl, kb + G_TILE);
#pragma unroll
                for (int ms = 0; ms < 2; ms++) {
                    mma16816(acc[ms][2 * g],     ah + 4 * ms, bh[0], bh[1]);
                    mma16816(acc[ms][2 * g + 1], ah + 4 * ms, bh[2], bh[3]);
                    mma16816(acc[ms][2 * g],     ah + 4 * ms, bl[0], bl[1]);
                    mma16816(acc[ms][2 * g + 1], ah + 4 * ms, bl[2], bl[3]);
                    mma16816(acc[ms][2 * g],     al + 4 * ms, bh[0], bh[1]);
                    mma16816(acc[ms][2 * g + 1], al + 4 * ms, bh[2], bh[3]);
                }
            }
        }
        __syncthreads();
        if (i + 2 < nch) {
            G_ISSUE(i + 2, cur);
            CP_COMMIT();
        }
    }
#undef G_ISSUE

    // ---------------- epilogues ----------------
    const int trow = lane >> 2;
    const int tcol = (lane & 3) * 2;

    if (MODE == 0) {
#pragma unroll
        for (int ms = 0; ms < 2; ms++) {
#pragma unroll
            for (int nf = 0; nf < 8; nf++) {
                const int r = bm + wm * 32 + ms * 16 + trow;
                const int c = bn + wn * 64 + nf * 8 + tcol;
                *(float2*)(C + (size_t)r * N + c) =
                    make_float2(acc[ms][nf][0], acc[ms][nf][1]);
                *(float2*)(C + (size_t)(r + 8) * N + c) =
                    make_float2(acc[ms][nf][2], acc[ms][nf][3]);
            }
        }
    } else {
        const int head = (bn + wn * 64) >> 6;
        const int nheads = (MODE == 1) ? NH : NKV;
        const float sc = (MODE == 1) ? (0.125f * 1.4426950408889634f) : 1.0f;
        ushort_t* gh = (MODE == 1) ? g_qh : (isV ? g_vh : g_kh);
        ushort_t* gl = (MODE == 1) ? g_ql : (isV ? g_vl : g_kl);
#pragma unroll
        for (int ms = 0; ms < 2; ms++) {
#pragma unroll
            for (int q2 = 0; q2 < 2; q2++) {
                const int token = bm + wm * 32 + ms * 16 + trow + q2 * 8;
                const int bb = token >> 11;
                const int tt = token & (Tdim - 1);
                const size_t obase =
                    ((size_t)(bb * nheads + head) * Tdim + tt) * HD;
                if (isV) {
#pragma unroll
                    for (int nf = 0; nf < 8; nf++) {
#pragma unroll
                        for (int qc = 0; qc < 2; qc++) {
                            const int d = nf * 8 + tcol + qc;
                            split_store(acc[ms][nf][q2 * 2 + qc],
                                        &gh[obase + d], &gl[obase + d]);
                        }
                    }
                } else {
#pragma unroll
                    for (int nf = 0; nf < 4; nf++) {
#pragma unroll
                        for (int qc = 0; qc < 2; qc++) {
                            const int d = nf * 8 + tcol + qc;   // 0..31
                            float x1 = acc[ms][nf][q2 * 2 + qc];
                            float x2 = acc[ms][nf + 4][q2 * 2 + qc];
                            float c = cosp[(size_t)token * HD + d];
                            float s = sinp[(size_t)token * HD + d];
                            float y1 = (x1 * c - x2 * s) * sc;
                            float y2 = (x2 * c + x1 * s) * sc;
                            split_store(y1, &gh[obase + d], &gl[obase + d]);
                            split_store(y2, &gh[obase + d + 32],
                                            &gl[obase + d + 32]);
                        }
                    }
                }
            }
        }
    }
}

// ---------------- Flash attention (tensor cores, cp.async K/V pipeline) -----
// Br=128, Bc=64, 256 threads (8 warps). Q resident; K/V double-buffered.
#define FB 144
#define FA_STAGE_B 36864
#define FA_SMEM (36864 + 2 * FA_STAGE_B)   // 110592

__global__ __launch_bounds__(256, 2) void flash_mma() {
    extern __shared__ ushort_t fsm[];
    const uint32_t s0 = smem_u32(fsm);
    const uint32_t sQh = s0, sQl = s0 + 18432;

    const int tid = threadIdx.x;
    const int lane = tid & 31;
    const int w = tid >> 5;
    const int qtile = (int)gridDim.x - 1 - (int)blockIdx.x;  // big first
    const int bh = blockIdx.y;
    const int b = bh / NH;
    const int h = bh % NH;
    const int kvh = h / (NH / NKV);

    const ushort_t* qhp = g_qh + ((size_t)bh * Tdim + qtile * 128) * HD;
    const ushort_t* qlp = g_ql + ((size_t)bh * Tdim + qtile * 128) * HD;
    const size_t kvbase = (size_t)(b * NKV + kvh) * Tdim * HD;
    const ushort_t* pkh = g_kh + kvbase;
    const ushort_t* pkl = g_kl + kvbase;
    const ushort_t* pvh = g_vh + kvbase;
    const ushort_t* pvl = g_vl + kvbase;

    const uint32_t d0 = (uint32_t)((tid >> 3) * FB + (tid & 7) * 16);
    const uint32_t d1 = (uint32_t)(((tid + 256) >> 3) * FB + (tid & 7) * 16);
    const uint32_t g0 = (uint32_t)((tid >> 3) * HD + (tid & 7) * 8);
    const uint32_t g1 = (uint32_t)(((tid + 256) >> 3) * HD + (tid & 7) * 8);

#define FA_ISSUE(kt, stg) do {                                                \
    const uint32_t _sb = s0 + 36864 + (uint32_t)(stg) * FA_STAGE_B;           \
    const size_t _go = (size_t)(kt) * 64 * HD;                                \
    CP_ASYNC(_sb + d0,         pkh + _go + g0);                               \
    CP_ASYNC(_sb + d1,         pkh + _go + g1);                               \
    CP_ASYNC(_sb + 9216 + d0,  pkl + _go + g0);                               \
    CP_ASYNC(_sb + 9216 + d1,  pkl + _go + g1);                               \
    CP_ASYNC(_sb + 18432 + d0, pvh + _go + g0);                               \
    CP_ASYNC(_sb + 18432 + d1, pvh + _go + g1);                               \
    CP_ASYNC(_sb + 27648 + d0, pvl + _go + g0);                               \
    CP_ASYNC(_sb + 27648 + d1, pvl + _go + g1);                               \
} while (0)

    FA_ISSUE(0, 0); CP_COMMIT();
    FA_ISSUE(1, 1); CP_COMMIT();

    // stage Q (128x64 bf16 x2)
#pragma unroll
    for (int j = 0; j < 4; j++) {
        const int idx = tid + j * 256;
        const int qr = idx >> 3;
        const int qc = idx & 7;
        *(uint4*)(fsm + qr * 72 + qc * 8)        = *(const uint4*)(qhp + qr * HD + qc * 8);
        *(uint4*)(fsm + 9216 + qr * 72 + qc * 8) = *(const uint4*)(qlp + qr * HD + qc * 8);
    }

    const int r8 = lane & 7, sub = lane >> 3;
    const uint32_t a_off = (uint32_t)((w * 16 + r8 + ((sub & 1) << 3)) * FB +
                                      ((sub >> 1) << 4));
    const uint32_t b_off = (uint32_t)((r8 + ((sub >> 1) << 3)) * FB +
                                      ((sub & 1) << 4));
    const uint32_t v_off = (uint32_t)(((lane & 8) + (lane & 7)) * FB +
                                      (lane >> 4) * 16);

    float m0 = -1e30f, m1 = -1e30f, l0 = 0.f, l1 = 0.f;
    float o[8][4];
#pragma unroll
    for (int t = 0; t < 8; t++)
#pragma unroll
        for (int e = 0; e < 4; e++) o[t][e] = 0.f;

    const int ktmax = 2 * qtile + 1;
    for (int kt = 0; kt <= ktmax; kt++) {
        const uint32_t stg = s0 + 36864 + (uint32_t)(kt & 1) * FA_STAGE_B;
        if (kt < ktmax) { CP_WAIT1(); } else { CP_WAIT0(); }
        __syncthreads();

        // on the last tile, warps 0-3 (rows 0-63 of the q-block) are entirely
        // above the diagonal -> p == 0, alpha == 1: skip all work exactly.
        if (kt < ktmax || w >= 4) {
            // --- S = Q K^T (3x split, base-2 logits) ---
            float sa[8][4];
#pragma unroll
            for (int t = 0; t < 8; t++)
#pragma unroll
                for (int e = 0; e < 4; e++) sa[t][e] = 0.f;

#pragma unroll
            for (int ks = 0; ks < 4; ks++) {
                uint32_t aqh[4], aql[4];
                ldm4(aqh, sQh + a_off + ks * 32);
                ldm4(aql, sQl + a_off + ks * 32);
#pragma unroll
                for (int g = 0; g < 4; g++) {
                    uint32_t kbh[4], kbl[4];
                    const uint32_t kb = stg + b_off + ks * 32 + g * (16 * FB);
                    ldm4(kbh, kb);
                    ldm4(kbl, kb + 9216);
                    mma16816(sa[2 * g],     aqh, kbh[0], kbh[1]);
                    mma16816(sa[2 * g + 1], aqh, kbh[2], kbh[3]);
                    mma16816(sa[2 * g],     aqh, kbl[0], kbl[1]);
                    mma16816(sa[2 * g + 1], aqh, kbl[2], kbl[3]);
                    mma16816(sa[2 * g],     aql, kbh[0], kbh[1]);
                    mma16816(sa[2 * g + 1], aql, kbh[2], kbh[3]);
                }
            }

            // --- causal mask (last two tiles only) ---
            if (kt >= 2 * qtile) {
                const int row0 = qtile * 128 + w * 16 + (lane >> 2);
                const int cb = kt * 64 + (lane & 3) * 2;
#pragma unroll
                for (int t = 0; t < 8; t++) {
                    const int c0 = cb + t * 8;
                    if (c0 > row0)         sa[t][0] = -1e30f;
                    if (c0 + 1 > row0)     sa[t][1] = -1e30f;
                    if (c0 > row0 + 8)     sa[t][2] = -1e30f;
                    if (c0 + 1 > row0 + 8) sa[t][3] = -1e30f;
                }
            }

            // --- online softmax (base 2) ---
            float rm0 = -1e30f, rm1 = -1e30f;
#pragma unroll
            for (int t = 0; t < 8; t++) {
                rm0 = fmaxf(rm0, fmaxf(sa[t][0], sa[t][1]));
                rm1 = fmaxf(rm1, fmaxf(sa[t][2], sa[t][3]));
            }
            rm0 = fmaxf(rm0, __shfl_xor_sync(0xffffffffu, rm0, 1));
            rm0 = fmaxf(rm0, __shfl_xor_sync(0xffffffffu, rm0, 2));
            rm1 = fmaxf(rm1, __shfl_xor_sync(0xffffffffu, rm1, 1));
            rm1 = fmaxf(rm1, __shfl_xor_sync(0xffffffffu, rm1, 2));
            const float mn0 = fmaxf(m0, rm0);
            const float mn1 = fmaxf(m1, rm1);
            const float al0 = ex2(m0 - mn0);
            const float al1 = ex2(m1 - mn1);
            m0 = mn0; m1 = mn1;
            float rs0 = 0.f, rs1 = 0.f;
#pragma unroll
            for (int t = 0; t < 8; t++) {
                sa[t][0] = ex2(sa[t][0] - mn0);
                sa[t][1] = ex2(sa[t][1] - mn0);
                sa[t][2] = ex2(sa[t][2] - mn1);
                sa[t][3] = ex2(sa[t][3] - mn1);
                rs0 += sa[t][0] + sa[t][1];
                rs1 += sa[t][2] + sa[t][3];
            }
            rs0 += __shfl_xor_sync(0xffffffffu, rs0, 1);
            rs0 += __shfl_xor_sync(0xffffffffu, rs0, 2);
            rs1 += __shfl_xor_sync(0xffffffffu, rs1, 1);
            rs1 += __shfl_xor_sync(0xffffffffu, rs1, 2);
            l0 = l0 * al0 + rs0;
            l1 = l1 * al1 + rs1;
#pragma unroll
            for (int t = 0; t < 8; t++) {
                o[t][0] *= al0; o[t][1] *= al0;
                o[t][2] *= al1; o[t][3] *= al1;
            }

            // --- O += P V (3x split); P packed per-kc ---
            const uint32_t sVh = stg + 18432;
#pragma unroll
            for (int kc = 0; kc < 4; kc++) {
                const int t0 = 2 * kc, t1 = 2 * kc + 1;
                uint32_t aph[4], apl[4];
                aph[0] = pack_hi(sa[t0][0], sa[t0][1]);
                aph[1] = pack_hi(sa[t0][2], sa[t0][3]);
                aph[2] = pack_hi(sa[t1][0], sa[t1][1]);
                aph[3] = pack_hi(sa[t1][2], sa[t1][3]);
                apl[0] = pack_lo(sa[t0][0], sa[t0][1]);
                apl[1] = pack_lo(sa[t0][2], sa[t0][3]);
                apl[2] = pack_lo(sa[t1][0], sa[t1][1]);
                apl[3] = pack_lo(sa[t1][2], sa[t1][3]);
#pragma unroll
                for (int tp = 0; tp < 4; tp++) {
                    uint32_t vbh[4], vbl[4];
                    const uint32_t va = sVh + v_off + kc * (16 * FB) + tp * 32;
                    ldm4t(vbh, va);
                    ldm4t(vbl, va + 9216);
                    mma16816(o[2 * tp],     aph, vbh[0], vbh[1]);
                    mma16816(o[2 * tp + 1], aph, vbh[2], vbh[3]);
                    mma16816(o[2 * tp],     aph, vbl[0], vbl[1]);
                    mma16816(o[2 * tp + 1], aph, vbl[2], vbl[3]);
                    mma16816(o[2 * tp],     apl, vbh[0], vbh[1]);
                    mma16816(o[2 * tp + 1], apl, vbh[2], vbh[3]);
                }
            }
        }

        __syncthreads();
        if (kt + 2 <= ktmax) {
            FA_ISSUE(kt + 2, kt & 1);
            CP_COMMIT();
        }
    }
#undef FA_ISSUE

    // epilogue: normalize + split-write for the O projection
    const float inv0 = 1.0f / l0;
    const float inv1 = 1.0f / l1;
    const int row0 = qtile * 128 + w * 16 + (lane >> 2);
    const int colb = (lane & 3) * 2;
#pragma unroll
    for (int t = 0; t < 8; t++) {
        const int c = h * HD + t * 8 + colb;
        const size_t i0 = ((size_t)b * Tdim + row0) * (NH * HD) + c;
        const size_t i1 = ((size_t)b * Tdim + row0 + 8) * (NH * HD) + c;
        float a0 = o[t][0] * inv0, a1 = o[t][1] * inv0;
        float a2 = o[t][2] * inv1, a3 = o[t][3] * inv1;
        *(uint32_t*)(g_oh + i0) = pack_hi(a0, a1);
        *(uint32_t*)(g_ol + i0) = pack_lo(a0, a1);
        *(uint32_t*)(g_oh + i1) = pack_hi(a2, a3);
        *(uint32_t*)(g_ol + i1) = pack_lo(a2, a3);
    }
}

// ---------------- launch ----------------------------------------------------
extern "C" void kernel_launch(void* const* d_in, const int* in_sizes, int n_in,
                              void* d_out, int out_size) {
    const float* hidden = (const float*)d_in[0];
    const float* cosp   = (const float*)d_in[1];
    const float* sinp   = (const float*)d_in[2];
    const float* wq     = (const float*)d_in[3];
    const float* wk     = (const float*)d_in[4];
    const float* wv     = (const float*)d_in[5];
    const float* wo     = (const float*)d_in[6];
    float* out = (float*)d_out;

    ushort_t *hh, *hl, *wqh, *wql, *wkh, *wkl, *wvh, *wvl, *woh, *wol, *oh, *ol;
    cudaGetSymbolAddress((void**)&hh,  g_hh);
    cudaGetSymbolAddress((void**)&hl,  g_hl);
    cudaGetSymbolAddress((void**)&wqh, g_wqh);
    cudaGetSymbolAddress((void**)&wql, g_wql);
    cudaGetSymbolAddress((void**)&wkh, g_wkh);
    cudaGetSymbolAddress((void**)&wkl, g_wkl);
    cudaGetSymbolAddress((void**)&wvh, g_wvh);
    cudaGetSymbolAddress((void**)&wvl, g_wvl);
    cudaGetSymbolAddress((void**)&woh, g_woh);
    cudaGetSymbolAddress((void**)&wol, g_wol);
    cudaGetSymbolAddress((void**)&oh,  g_oh);
    cudaGetSymbolAddress((void**)&ol,  g_ol);

    cudaFuncSetAttribute(gemm_fused<0>, cudaFuncAttributeMaxDynamicSharedMemorySize, G_SMEM);
    cudaFuncSetAttribute(gemm_fused<1>, cudaFuncAttributeMaxDynamicSharedMemorySize, G_SMEM);
    cudaFuncSetAttribute(gemm_fused<2>, cudaFuncAttributeMaxDynamicSharedMemorySize, G_SMEM);
    cudaFuncSetAttribute(flash_mma, cudaFuncAttributeMaxDynamicSharedMemorySize, FA_SMEM);

    // pre-split inputs (bf16 hi/lo)
    split_f32<<<(BT * HID / 4 + 255) / 256, 256>>>(hidden, hh, hl, BT * HID / 4);
    split_f32<<<(HID * HID / 4 + 255) / 256, 256>>>(wq, wqh, wql, HID * HID / 4);
    split_f32<<<(NKV * HD * HID / 4 + 255) / 256, 256>>>(wk, wkh, wkl, NKV * HD * HID / 4);
    split_f32<<<(NKV * HD * HID / 4 + 255) / 256, 256>>>(wv, wvh, wvl, NKV * HD * HID / 4);
    split_f32<<<(HID * HID / 4 + 255) / 256, 256>>>(wo, woh, wol, HID * HID / 4);

    // Q projection with fused rope+scale+split
    gemm_fused<1><<<dim3(16, 32), 256, G_SMEM>>>(
        hh, hl, wqh, wql, nullptr, nullptr, nullptr, cosp, sinp, NH * HD, HID);

    // K (rope+split) and V (split) projections in one launch
    gemm_fused<2><<<dim3(8, 32), 256, G_SMEM>>>(
        hh, hl, wkh, wkl, wvh, wvl, nullptr, cosp, sinp, NKV * HD, HID);

    // Flash attention (tensor cores)
    flash_mma<<<dim3(Tdim / 128, Bdim * NH), 256, FA_SMEM>>>();

    // Output projection (plain fp32 epilogue)
    gemm_fused<0><<<dim3(16, 32), 256, G_SMEM>>>(
        oh, ol, woh, wol, nullptr, nullptr, out, nullptr, nullptr, HID, HID);
}

// round 13
// speedup vs baseline: 1.2058x; 1.1685x over previous
#include <cuda_runtime.h>
#include <cstdint>
#include <math.h>

#define Bdim 2
#define Tdim 2048
#define HID 2048
#define NH 32
#define NKV 8
#define HD 64
#define BT (Bdim * Tdim)   // 4096

typedef unsigned short ushort_t;

// ---------------- scratch (device globals; no allocations allowed) ----------
__device__ __align__(16) ushort_t g_hh[(size_t)BT * HID];
__device__ __align__(16) ushort_t g_hl[(size_t)BT * HID];
__device__ __align__(16) ushort_t g_wqh[(size_t)NH * HD * HID];
__device__ __align__(16) ushort_t g_wql[(size_t)NH * HD * HID];
__device__ __align__(16) ushort_t g_wkh[(size_t)NKV * HD * HID];
__device__ __align__(16) ushort_t g_wkl[(size_t)NKV * HD * HID];
__device__ __align__(16) ushort_t g_wvh[(size_t)NKV * HD * HID];
__device__ __align__(16) ushort_t g_wvl[(size_t)NKV * HD * HID];
__device__ __align__(16) ushort_t g_woh[(size_t)HID * NH * HD];
__device__ __align__(16) ushort_t g_wol[(size_t)HID * NH * HD];
// attention operands in fp16 (single precision path, mma f16)
__device__ __align__(16) ushort_t g_qf[(size_t)Bdim * NH  * Tdim * HD];
__device__ __align__(16) ushort_t g_kf[(size_t)Bdim * NKV * Tdim * HD];
__device__ __align__(16) ushort_t g_vf[(size_t)Bdim * NKV * Tdim * HD];
// attention output, split bf16 for the (3-term) O projection
__device__ __align__(16) ushort_t g_oh[(size_t)BT * NH * HD];
__device__ __align__(16) ushort_t g_ol[(size_t)BT * NH * HD];

// ======================= helpers ============================================
static __device__ __forceinline__ uint32_t smem_u32(const void* p) {
    uint32_t a;
    asm("{ .reg .u64 t; cvta.to.shared.u64 t, %1; cvt.u32.u64 %0, t; }"
        : "=r"(a) : "l"(p));
    return a;
}

static __device__ __forceinline__ void ldm4(uint32_t* r, uint32_t addr) {
    asm volatile("ldmatrix.sync.aligned.m8n8.x4.shared.b16 {%0,%1,%2,%3}, [%4];"
                 : "=r"(r[0]), "=r"(r[1]), "=r"(r[2]), "=r"(r[3]) : "r"(addr));
}

static __device__ __forceinline__ void ldm4t(uint32_t* r, uint32_t addr) {
    asm volatile("ldmatrix.sync.aligned.m8n8.x4.trans.shared.b16 {%0,%1,%2,%3}, [%4];"
                 : "=r"(r[0]), "=r"(r[1]), "=r"(r[2]), "=r"(r[3]) : "r"(addr));
}

// bf16 x bf16 -> f32
static __device__ __forceinline__ void mma16816(float* c, const uint32_t* a,
                                                uint32_t b0, uint32_t b1) {
    asm volatile("mma.sync.aligned.m16n8k16.row.col.f32.bf16.bf16.f32 "
                 "{%0,%1,%2,%3}, {%4,%5,%6,%7}, {%8,%9}, {%0,%1,%2,%3};"
                 : "+f"(c[0]), "+f"(c[1]), "+f"(c[2]), "+f"(c[3])
                 : "r"(a[0]), "r"(a[1]), "r"(a[2]), "r"(a[3]), "r"(b0), "r"(b1));
}

// f16 x f16 -> f32
static __device__ __forceinline__ void mma16816h(float* c, const uint32_t* a,
                                                 uint32_t b0, uint32_t b1) {
    asm volatile("mma.sync.aligned.m16n8k16.row.col.f32.f16.f16.f32 "
                 "{%0,%1,%2,%3}, {%4,%5,%6,%7}, {%8,%9}, {%0,%1,%2,%3};"
                 : "+f"(c[0]), "+f"(c[1]), "+f"(c[2]), "+f"(c[3])
                 : "r"(a[0]), "r"(a[1]), "r"(a[2]), "r"(a[3]), "r"(b0), "r"(b1));
}

static __device__ __forceinline__ uint32_t pack_hi(float a, float b) {
    return __byte_perm(__float_as_uint(a), __float_as_uint(b), 0x7632);
}
static __device__ __forceinline__ uint32_t pack_lo(float a, float b) {
    float ra = a - __uint_as_float(__float_as_uint(a) & 0xFFFF0000u);
    float rb = b - __uint_as_float(__float_as_uint(b) & 0xFFFF0000u);
    uint32_t r;
    asm("cvt.rn.satfinite.bf16x2.f32 %0, %1, %2;" : "=r"(r) : "f"(rb), "f"(ra));
    return r;
}
// pack two floats as f16x2 (low = a, high = b)
static __device__ __forceinline__ uint32_t pack_f16(float a, float b) {
    uint32_t r;
    asm("cvt.rn.f16x2.f32 %0, %1, %2;" : "=r"(r) : "f"(b), "f"(a));
    return r;
}
static __device__ __forceinline__ ushort_t f16(float x) {
    ushort_t r;
    asm("cvt.rn.f16.f32 %0, %1;" : "=h"(r) : "f"(x));
    return r;
}

static __device__ __forceinline__ float ex2(float x) {
    float r;
    asm("ex2.approx.f32 %0, %1;" : "=f"(r) : "f"(x));
    return r;
}

#define CP_ASYNC(dst, src) \
    asm volatile("cp.async.cg.shared.global [%0], [%1], 16;" \
                 :: "r"(dst), "l"(src) : "memory")
#define CP_COMMIT() asm volatile("cp.async.commit_group;" ::: "memory")
#define CP_WAIT1() asm volatile("cp.async.wait_group 1;" ::: "memory")
#define CP_WAIT0() asm volatile("cp.async.wait_group 0;" ::: "memory")

// ---------------- input pre-split ------------------------------------------
__global__ __launch_bounds__(256) void split_f32(const float* __restrict__ src,
                                                 ushort_t* __restrict__ hi,
                                                 ushort_t* __restrict__ lo,
                                                 int n4) {
    int i = blockIdx.x * blockDim.x + threadIdx.x;
    if (i < n4) {
        float4 f = ((const float4*)src)[i];
        ((uint2*)hi)[i] = make_uint2(pack_hi(f.x, f.y), pack_hi(f.z, f.w));
        ((uint2*)lo)[i] = make_uint2(pack_lo(f.x, f.y), pack_lo(f.z, f.w));
    }
}

// =============== mma.sync GEMM with fused epilogues =========================
// C[M,N] = (Ah+Al)[M,K] * (Bh+Bl)[N,K]^T, 3-term bf16 split, fp32 accum.
// MODE 0: store fp32 C. MODE 1: rope+scale -> fp16 g_qf.
// MODE 2: blockIdx.x<4 -> K rope -> fp16 g_kf; else V -> fp16 g_vf.
#define G_ROWB 80
#define G_TILE 10240
#define G_STAGE_B (4 * G_TILE)
#define G_SMEM (2 * G_STAGE_B + 128)

template<int MODE>
__global__ __launch_bounds__(256, 2) void gemm_fused(
    const ushort_t* __restrict__ Ah, const ushort_t* __restrict__ Al,
    const ushort_t* __restrict__ Bh1, const ushort_t* __restrict__ Bl1,
    const ushort_t* __restrict__ Bh2, const ushort_t* __restrict__ Bl2,
    float* __restrict__ C,
    const float* __restrict__ cosp, const float* __restrict__ sinp,
    int N, int K) {
    extern __shared__ char dsm[];
    const uint32_t tile = (smem_u32(dsm) + 127u) & ~127u;

    const int tid = threadIdx.x;
    const int wid = tid >> 5;
    const int lane = tid & 31;
    const int wm = wid & 3;
    const int wn = wid >> 2;
    const bool isV = (MODE == 2) && (blockIdx.x >= 4);
    const int bnx = isV ? ((int)blockIdx.x - 4) : (int)blockIdx.x;
    const int bm = blockIdx.y * 128;
    const int bn = bnx * 128;
    const ushort_t* Bh = isV ? Bh2 : Bh1;
    const ushort_t* Bl = isV ? Bl2 : Bl1;

    const int row = tid >> 1;
    const int half = tid & 1;
    const ushort_t* pAh = Ah + (size_t)(bm + row) * K + half * 16;
    const ushort_t* pAl = Al + (size_t)(bm + row) * K + half * 16;
    const ushort_t* pBh = Bh + (size_t)(bn + row) * K + half * 16;
    const ushort_t* pBl = Bl + (size_t)(bn + row) * K + half * 16;
    const uint32_t s_row = (uint32_t)(row * G_ROWB + half * 32);

    const int r8 = lane & 7, sub = lane >> 3;
    const uint32_t a_off = (uint32_t)((wm * 32 + r8 + (sub & 1) * 8) * G_ROWB +
                                      (sub >> 1) * 16);
    const uint32_t b_off = (uint32_t)((wn * 64 + r8 + (sub >> 1) * 8) * G_ROWB +
                                      (sub & 1) * 16);

    float acc[2][8][4];
#pragma unroll
    for (int i = 0; i < 2; i++)
#pragma unroll
        for (int j = 0; j < 8; j++)
#pragma unroll
            for (int q = 0; q < 4; q++) acc[i][j][q] = 0.f;

    const int nch = K >> 5;

#define G_ISSUE(chunk, sb) do {                                               \
    const int _k0 = (chunk) << 5;                                             \
    CP_ASYNC((sb) + s_row,                   pAh + _k0);                      \
    CP_ASYNC((sb) + s_row + 16,              pAh + _k0 + 8);                  \
    CP_ASYNC((sb) + G_TILE + s_row,          pAl + _k0);                      \
    CP_ASYNC((sb) + G_TILE + s_row + 16,     pAl + _k0 + 8);                  \
    CP_ASYNC((sb) + 2 * G_TILE + s_row,      pBh + _k0);                      \
    CP_ASYNC((sb) + 2 * G_TILE + s_row + 16, pBh + _k0 + 8);                  \
    CP_ASYNC((sb) + 3 * G_TILE + s_row,      pBl + _k0);                      \
    CP_ASYNC((sb) + 3 * G_TILE + s_row + 16, pBl + _k0 + 8);                  \
} while (0)

    G_ISSUE(0, tile);              CP_COMMIT();
    G_ISSUE(1, tile + G_STAGE_B);  CP_COMMIT();

    for (int i = 0; i < nch; i++) {
        const uint32_t cur = tile + (uint32_t)(i & 1) * G_STAGE_B;
        if (i + 1 < nch) { CP_WAIT1(); } else { CP_WAIT0(); }
        __syncthreads();

#pragma unroll
        for (int ks = 0; ks < 2; ks++) {
            uint32_t ah[8], al[8];
            const uint32_t ka = cur + a_off + ks * 32;
            ldm4(ah,     ka);
            ldm4(ah + 4, ka + 16 * G_ROWB);
            ldm4(al,     ka + G_TILE);
            ldm4(al + 4, ka + G_TILE + 16 * G_ROWB);
#pragma unroll
            for (int g = 0; g < 4; g++) {
                uint32_t bh[4], bl[4];
                const uint32_t kb = cur + 2 * G_TILE + b_off + ks * 32 +
                                    g * (16 * G_ROWB);
                ldm4(bh, kb);
                ldm4(bl, kb + G_TILE);
#pragma unroll
                for (int ms = 0; ms < 2; ms++) {
                    mma16816(acc[ms][2 * g],     ah + 4 * ms, bh[0], bh[1]);
                    mma16816(acc[ms][2 * g + 1], ah + 4 * ms, bh[2], bh[3]);
                    mma16816(acc[ms][2 * g],     ah + 4 * ms, bl[0], bl[1]);
                    mma16816(acc[ms][2 * g + 1], ah + 4 * ms, bl[2], bl[3]);
                    mma16816(acc[ms][2 * g],     al + 4 * ms, bh[0], bh[1]);
                    mma16816(acc[ms][2 * g + 1], al + 4 * ms, bh[2], bh[3]);
                }
            }
        }
        __syncthreads();
        if (i + 2 < nch) {
            G_ISSUE(i + 2, cur);
            CP_COMMIT();
        }
    }
#undef G_ISSUE

    // ---------------- epilogues ----------------
    const int trow = lane >> 2;
    const int tcol = (lane & 3) * 2;

    if (MODE == 0) {
#pragma unroll
        for (int ms = 0; ms < 2; ms++) {
#pragma unroll
            for (int nf = 0; nf < 8; nf++) {
                const int r = bm + wm * 32 + ms * 16 + trow;
                const int c = bn + wn * 64 + nf * 8 + tcol;
                *(float2*)(C + (size_t)r * N + c) =
                    make_float2(acc[ms][nf][0], acc[ms][nf][1]);
                *(float2*)(C + (size_t)(r + 8) * N + c) =
                    make_float2(acc[ms][nf][2], acc[ms][nf][3]);
            }
        }
    } else {
        const int head = (bn + wn * 64) >> 6;
        const int nheads = (MODE == 1) ? NH : NKV;
        const float sc = (MODE == 1) ? (0.125f * 1.4426950408889634f) : 1.0f;
        ushort_t* gf = (MODE == 1) ? g_qf : (isV ? g_vf : g_kf);
#pragma unroll
        for (int ms = 0; ms < 2; ms++) {
#pragma unroll
            for (int q2 = 0; q2 < 2; q2++) {
                const int token = bm + wm * 32 + ms * 16 + trow + q2 * 8;
                const int bb = token >> 11;
                const int tt = token & (Tdim - 1);
                const size_t obase =
                    ((size_t)(bb * nheads + head) * Tdim + tt) * HD;
                if (isV) {
#pragma unroll
                    for (int nf = 0; nf < 8; nf++) {
#pragma unroll
                        for (int qc = 0; qc < 2; qc++) {
                            const int d = nf * 8 + tcol + qc;
                            gf[obase + d] = f16(acc[ms][nf][q2 * 2 + qc]);
                        }
                    }
                } else {
#pragma unroll
                    for (int nf = 0; nf < 4; nf++) {
#pragma unroll
                        for (int qc = 0; qc < 2; qc++) {
                            const int d = nf * 8 + tcol + qc;   // 0..31
                            float x1 = acc[ms][nf][q2 * 2 + qc];
                            float x2 = acc[ms][nf + 4][q2 * 2 + qc];
                            float c = cosp[(size_t)token * HD + d];
                            float s = sinp[(size_t)token * HD + d];
                            gf[obase + d]      = f16((x1 * c - x2 * s) * sc);
                            gf[obase + d + 32] = f16((x2 * c + x1 * s) * sc);
                        }
                    }
                }
            }
        }
    }
}

// ---------------- Flash attention (fp16 tensor cores, cp.async pipeline) ----
// Br=128, Bc=64, 256 threads (8 warps). Q resident fp16; K/V double-buffered.
// smem ushort layout: Q [0, 9216); stage s at 9216 + s*9216: K 4608, V 4608.
#define FB 144
#define FA_STAGE_EL 9216            // ushorts per stage (K + V)
#define FA_SMEM ((9216 + 2 * 9216) * 2)   // 55296 bytes

__global__ __launch_bounds__(256, 2) void flash_mma() {
    extern __shared__ ushort_t fsm[];
    const uint32_t s0 = smem_u32(fsm);
    const uint32_t sQ = s0;

    const int tid = threadIdx.x;
    const int lane = tid & 31;
    const int w = tid >> 5;
    const int qtile = (int)gridDim.x - 1 - (int)blockIdx.x;  // big first
    const int bh = blockIdx.y;
    const int b = bh / NH;
    const int h = bh % NH;
    const int kvh = h / (NH / NKV);

    const ushort_t* qp = g_qf + ((size_t)bh * Tdim + qtile * 128) * HD;
    const size_t kvbase = (size_t)(b * NKV + kvh) * Tdim * HD;
    const ushort_t* pk = g_kf + kvbase;
    const ushort_t* pv = g_vf + kvbase;

    // per-thread load mapping for one 64x64 fp16 tile: 2 x 16B per array
    const uint32_t d0 = (uint32_t)((tid >> 3) * FB + (tid & 7) * 16);
    const uint32_t d1 = (uint32_t)(((tid + 256) >> 3) * FB + (tid & 7) * 16);
    const uint32_t g0 = (uint32_t)((tid >> 3) * HD + (tid & 7) * 8);
    const uint32_t g1 = (uint32_t)(((tid + 256) >> 3) * HD + (tid & 7) * 8);

#define FA_ISSUE(kt, stg) do {                                                \
    const uint32_t _sb = s0 + 18432 + (uint32_t)(stg) * 18432;                \
    const size_t _go = (size_t)(kt) * 64 * HD;                                \
    CP_ASYNC(_sb + d0,        pk + _go + g0);                                 \
    CP_ASYNC(_sb + d1,        pk + _go + g1);                                 \
    CP_ASYNC(_sb + 9216 + d0, pv + _go + g0);                                 \
    CP_ASYNC(_sb + 9216 + d1, pv + _go + g1);                                 \
} while (0)

    FA_ISSUE(0, 0); CP_COMMIT();
    FA_ISSUE(1, 1); CP_COMMIT();

    // stage Q (128x64 fp16): 1024 uint4, 4 per thread
#pragma unroll
    for (int j = 0; j < 4; j++) {
        const int idx = tid + j * 256;
        const int qr = idx >> 3;
        const int qc = idx & 7;
        *(uint4*)(fsm + qr * 72 + qc * 8) = *(const uint4*)(qp + qr * HD + qc * 8);
    }

    const int r8 = lane & 7, sub = lane >> 3;
    const uint32_t a_off = (uint32_t)((w * 16 + r8 + ((sub & 1) << 3)) * FB +
                                      ((sub >> 1) << 4));
    const uint32_t b_off = (uint32_t)((r8 + ((sub >> 1) << 3)) * FB +
                                      ((sub & 1) << 4));
    const uint32_t v_off = (uint32_t)(((lane & 8) + (lane & 7)) * FB +
                                      (lane >> 4) * 16);

    float m0 = -1e30f, m1 = -1e30f, l0 = 0.f, l1 = 0.f;
    float o[8][4];
#pragma unroll
    for (int t = 0; t < 8; t++)
#pragma unroll
        for (int e = 0; e < 4; e++) o[t][e] = 0.f;

    const int ktmax = 2 * qtile + 1;
    for (int kt = 0; kt <= ktmax; kt++) {
        const uint32_t stgK = s0 + 18432 + (uint32_t)(kt & 1) * 18432;
        const uint32_t stgV = stgK + 9216;
        if (kt < ktmax) { CP_WAIT1(); } else { CP_WAIT0(); }
        __syncthreads();

        // last tile: warps 0-3 fully above diagonal -> exact no-op
        if (kt < ktmax || w >= 4) {
            // --- S = Q K^T (fp16, base-2 logits) ---
            float sa[8][4];
#pragma unroll
            for (int t = 0; t < 8; t++)
#pragma unroll
                for (int e = 0; e < 4; e++) sa[t][e] = 0.f;

#pragma unroll
            for (int ks = 0; ks < 4; ks++) {
                uint32_t aq[4];
                ldm4(aq, sQ + a_off + ks * 32);
#pragma unroll
                for (int g = 0; g < 4; g++) {
                    uint32_t kb[4];
                    ldm4(kb, stgK + b_off + ks * 32 + g * (16 * FB));
                    mma16816h(sa[2 * g],     aq, kb[0], kb[1]);
                    mma16816h(sa[2 * g + 1], aq, kb[2], kb[3]);
                }
            }

            // --- causal mask (last two tiles only) ---
            if (kt >= 2 * qtile) {
                const int row0 = qtile * 128 + w * 16 + (lane >> 2);
                const int cb = kt * 64 + (lane & 3) * 2;
#pragma unroll
                for (int t = 0; t < 8; t++) {
                    const int c0 = cb + t * 8;
                    if (c0 > row0)         sa[t][0] = -1e30f;
                    if (c0 + 1 > row0)     sa[t][1] = -1e30f;
                    if (c0 > row0 + 8)     sa[t][2] = -1e30f;
                    if (c0 + 1 > row0 + 8) sa[t][3] = -1e30f;
                }
            }

            // --- online softmax (base 2) ---
            float rm0 = -1e30f, rm1 = -1e30f;
#pragma unroll
            for (int t = 0; t < 8; t++) {
                rm0 = fmaxf(rm0, fmaxf(sa[t][0], sa[t][1]));
                rm1 = fmaxf(rm1, fmaxf(sa[t][2], sa[t][3]));
            }
            rm0 = fmaxf(rm0, __shfl_xor_sync(0xffffffffu, rm0, 1));
            rm0 = fmaxf(rm0, __shfl_xor_sync(0xffffffffu, rm0, 2));
            rm1 = fmaxf(rm1, __shfl_xor_sync(0xffffffffu, rm1, 1));
            rm1 = fmaxf(rm1, __shfl_xor_sync(0xffffffffu, rm1, 2));
            const float mn0 = fmaxf(m0, rm0);
            const float mn1 = fmaxf(m1, rm1);
            const float al0 = ex2(m0 - mn0);
            const float al1 = ex2(m1 - mn1);
            m0 = mn0; m1 = mn1;
            float rs0 = 0.f, rs1 = 0.f;
#pragma unroll
            for (int t = 0; t < 8; t++) {
                sa[t][0] = ex2(sa[t][0] - mn0);
                sa[t][1] = ex2(sa[t][1] - mn0);
                sa[t][2] = ex2(sa[t][2] - mn1);
                sa[t][3] = ex2(sa[t][3] - mn1);
                rs0 += sa[t][0] + sa[t][1];
                rs1 += sa[t][2] + sa[t][3];
            }
            rs0 += __shfl_xor_sync(0xffffffffu, rs0, 1);
            rs0 += __shfl_xor_sync(0xffffffffu, rs0, 2);
            rs1 += __shfl_xor_sync(0xffffffffu, rs1, 1);
            rs1 += __shfl_xor_sync(0xffffffffu, rs1, 2);
            l0 = l0 * al0 + rs0;
            l1 = l1 * al1 + rs1;
#pragma unroll
            for (int t = 0; t < 8; t++) {
                o[t][0] *= al0; o[t][1] *= al0;
                o[t][2] *= al1; o[t][3] *= al1;
            }

            // --- O += P V (fp16 P, fp16 V) ---
#pragma unroll
            for (int kc = 0; kc < 4; kc++) {
                const int t0 = 2 * kc, t1 = 2 * kc + 1;
                uint32_t ap[4];
                ap[0] = pack_f16(sa[t0][0], sa[t0][1]);
                ap[1] = pack_f16(sa[t0][2], sa[t0][3]);
                ap[2] = pack_f16(sa[t1][0], sa[t1][1]);
                ap[3] = pack_f16(sa[t1][2], sa[t1][3]);
#pragma unroll
                for (int tp = 0; tp < 4; tp++) {
                    uint32_t vb[4];
                    ldm4t(vb, stgV + v_off + kc * (16 * FB) + tp * 32);
                    mma16816h(o[2 * tp],     ap, vb[0], vb[1]);
                    mma16816h(o[2 * tp + 1], ap, vb[2], vb[3]);
                }
            }
        }

        __syncthreads();
        if (kt + 2 <= ktmax) {
            FA_ISSUE(kt + 2, kt & 1);
            CP_COMMIT();
        }
    }
#undef FA_ISSUE

    // epilogue: normalize + bf16 split-write for the O projection
    const float inv0 = 1.0f / l0;
    const float inv1 = 1.0f / l1;
    const int row0 = qtile * 128 + w * 16 + (lane >> 2);
    const int colb = (lane & 3) * 2;
#pragma unroll
    for (int t = 0; t < 8; t++) {
        const int c = h * HD + t * 8 + colb;
        const size_t i0 = ((size_t)b * Tdim + row0) * (NH * HD) + c;
        const size_t i1 = ((size_t)b * Tdim + row0 + 8) * (NH * HD) + c;
        float a0 = o[t][0] * inv0, a1 = o[t][1] * inv0;
        float a2 = o[t][2] * inv1, a3 = o[t][3] * inv1;
        *(uint32_t*)(g_oh + i0) = pack_hi(a0, a1);
        *(uint32_t*)(g_ol + i0) = pack_lo(a0, a1);
        *(uint32_t*)(g_oh + i1) = pack_hi(a2, a3);
        *(uint32_t*)(g_ol + i1) = pack_lo(a2, a3);
    }
}

// ---------------- launch ----------------------------------------------------
extern "C" void kernel_launch(void* const* d_in, const int* in_sizes, int n_in,
                              void* d_out, int out_size) {
    const float* hidden = (const float*)d_in[0];
    const float* cosp   = (const float*)d_in[1];
    const float* sinp   = (const float*)d_in[2];
    const float* wq     = (const float*)d_in[3];
    const float* wk     = (const float*)d_in[4];
    const float* wv     = (const float*)d_in[5];
    const float* wo     = (const float*)d_in[6];
    float* out = (float*)d_out;

    ushort_t *hh, *hl, *wqh, *wql, *wkh, *wkl, *wvh, *wvl, *woh, *wol, *oh, *ol;
    cudaGetSymbolAddress((void**)&hh,  g_hh);
    cudaGetSymbolAddress((void**)&hl,  g_hl);
    cudaGetSymbolAddress((void**)&wqh, g_wqh);
    cudaGetSymbolAddress((void**)&wql, g_wql);
    cudaGetSymbolAddress((void**)&wkh, g_wkh);
    cudaGetSymbolAddress((void**)&wkl, g_wkl);
    cudaGetSymbolAddress((void**)&wvh, g_wvh);
    cudaGetSymbolAddress((void**)&wvl, g_wvl);
    cudaGetSymbolAddress((void**)&woh, g_woh);
    cudaGetSymbolAddress((void**)&wol, g_wol);
    cudaGetSymbolAddress((void**)&oh,  g_oh);
    cudaGetSymbolAddress((void**)&ol,  g_ol);

    cudaFuncSetAttribute(gemm_fused<0>, cudaFuncAttributeMaxDynamicSharedMemorySize, G_SMEM);
    cudaFuncSetAttribute(gemm_fused<1>, cudaFuncAttributeMaxDynamicSharedMemorySize, G_SMEM);
    cudaFuncSetAttribute(gemm_fused<2>, cudaFuncAttributeMaxDynamicSharedMemorySize, G_SMEM);
    cudaFuncSetAttribute(flash_mma, cudaFuncAttributeMaxDynamicSharedMemorySize, FA_SMEM);

    // pre-split inputs (bf16 hi/lo)
    split_f32<<<(BT * HID / 4 + 255) / 256, 256>>>(hidden, hh, hl, BT * HID / 4);
    split_f32<<<(HID * HID / 4 + 255) / 256, 256>>>(wq, wqh, wql, HID * HID / 4);
    split_f32<<<(NKV * HD * HID / 4 + 255) / 256, 256>>>(wk, wkh, wkl, NKV * HD * HID / 4);
    split_f32<<<(NKV * HD * HID / 4 + 255) / 256, 256>>>(wv, wvh, wvl, NKV * HD * HID / 4);
    split_f32<<<(HID * HID / 4 + 255) / 256, 256>>>(wo, woh, wol, HID * HID / 4);

    // Q projection with fused rope+scale -> fp16
    gemm_fused<1><<<dim3(16, 32), 256, G_SMEM>>>(
        hh, hl, wqh, wql, nullptr, nullptr, nullptr, cosp, sinp, NH * HD, HID);

    // K (rope) and V projections -> fp16, one launch
    gemm_fused<2><<<dim3(8, 32), 256, G_SMEM>>>(
        hh, hl, wkh, wkl, wvh, wvl, nullptr, cosp, sinp, NKV * HD, HID);

    // Flash attention (fp16 tensor cores)
    flash_mma<<<dim3(Tdim / 128, Bdim * NH), 256, FA_SMEM>>>();

    // Output projection (3-term bf16, fp32 epilogue)
    gemm_fused<0><<<dim3(16, 32), 256, G_SMEM>>>(
        oh, ol, woh, wol, nullptr, nullptr, out, nullptr, nullptr, HID, HID);
}

// round 14
// speedup vs baseline: 2.2354x; 1.8539x over previous
#include <cuda_runtime.h>
#include <cstdint>
#include <math.h>

#define Bdim 2
#define Tdim 2048
#define HID 2048
#define NH 32
#define NKV 8
#define HD 64
#define BT (Bdim * Tdim)   // 4096

typedef unsigned short ushort_t;

// ---------------- scratch (device globals; no allocations allowed) ----------
__device__ __align__(16) ushort_t g_hf [(size_t)BT * HID];          // hidden fp16
__device__ __align__(16) ushort_t g_wqf[(size_t)NH * HD * HID];
__device__ __align__(16) ushort_t g_wkf[(size_t)NKV * HD * HID];
__device__ __align__(16) ushort_t g_wvf[(size_t)NKV * HD * HID];
__device__ __align__(16) ushort_t g_wof[(size_t)HID * NH * HD];
// attention operands in fp16
__device__ __align__(16) ushort_t g_qf[(size_t)Bdim * NH  * Tdim * HD];
__device__ __align__(16) ushort_t g_kf[(size_t)Bdim * NKV * Tdim * HD];
__device__ __align__(16) ushort_t g_vf[(size_t)Bdim * NKV * Tdim * HD];
// attention output fp16 for the O projection
__device__ __align__(16) ushort_t g_of[(size_t)BT * NH * HD];

// ======================= helpers ============================================
static __device__ __forceinline__ uint32_t smem_u32(const void* p) {
    uint32_t a;
    asm("{ .reg .u64 t; cvta.to.shared.u64 t, %1; cvt.u32.u64 %0, t; }"
        : "=r"(a) : "l"(p));
    return a;
}

static __device__ __forceinline__ void ldm4(uint32_t* r, uint32_t addr) {
    asm volatile("ldmatrix.sync.aligned.m8n8.x4.shared.b16 {%0,%1,%2,%3}, [%4];"
                 : "=r"(r[0]), "=r"(r[1]), "=r"(r[2]), "=r"(r[3]) : "r"(addr));
}

static __device__ __forceinline__ void ldm4t(uint32_t* r, uint32_t addr) {
    asm volatile("ldmatrix.sync.aligned.m8n8.x4.trans.shared.b16 {%0,%1,%2,%3}, [%4];"
                 : "=r"(r[0]), "=r"(r[1]), "=r"(r[2]), "=r"(r[3]) : "r"(addr));
}

// f16 x f16 -> f32
static __device__ __forceinline__ void mma16816h(float* c, const uint32_t* a,
                                                 uint32_t b0, uint32_t b1) {
    asm volatile("mma.sync.aligned.m16n8k16.row.col.f32.f16.f16.f32 "
                 "{%0,%1,%2,%3}, {%4,%5,%6,%7}, {%8,%9}, {%0,%1,%2,%3};"
                 : "+f"(c[0]), "+f"(c[1]), "+f"(c[2]), "+f"(c[3])
                 : "r"(a[0]), "r"(a[1]), "r"(a[2]), "r"(a[3]), "r"(b0), "r"(b1));
}

// pack two floats as f16x2 (low = a, high = b)
static __device__ __forceinline__ uint32_t pack_f16(float a, float b) {
    uint32_t r;
    asm("cvt.rn.f16x2.f32 %0, %1, %2;" : "=r"(r) : "f"(b), "f"(a));
    return r;
}
static __device__ __forceinline__ ushort_t f16(float x) {
    ushort_t r;
    asm("cvt.rn.f16.f32 %0, %1;" : "=h"(r) : "f"(x));
    return r;
}

static __device__ __forceinline__ float ex2(float x) {
    float r;
    asm("ex2.approx.f32 %0, %1;" : "=f"(r) : "f"(x));
    return r;
}

#define CP_ASYNC(dst, src) \
    asm volatile("cp.async.cg.shared.global [%0], [%1], 16;" \
                 :: "r"(dst), "l"(src) : "memory")
#define CP_COMMIT() asm volatile("cp.async.commit_group;" ::: "memory")
#define CP_WAIT1() asm volatile("cp.async.wait_group 1;" ::: "memory")
#define CP_WAIT0() asm volatile("cp.async.wait_group 0;" ::: "memory")

// ---------------- fp32 -> fp16 convert --------------------------------------
__global__ __launch_bounds__(256) void cvt_f16(const float* __restrict__ src,
                                               ushort_t* __restrict__ dst,
                                               int n4) {
    int i = blockIdx.x * blockDim.x + threadIdx.x;
    if (i < n4) {
        float4 f = ((const float4*)src)[i];
        ((uint2*)dst)[i] = make_uint2(pack_f16(f.x, f.y), pack_f16(f.z, f.w));
    }
}

// =============== fp16 mma.sync GEMM with fused epilogues ====================
// C[M,N] = A[M,K] * B[N,K]^T, single-term fp16, fp32 accum.
// MODE 0: store fp32 C. MODE 1: rope+scale -> fp16 g_qf.
// MODE 2: blockIdx.x<4 -> K rope -> fp16 g_kf; else V -> fp16 g_vf.
#define G_ROWB 80
#define G_TILE 10240
#define G_STAGE_B (2 * G_TILE)          // A + B tiles = 20480
#define G_SMEM (2 * G_STAGE_B + 128)    // 41088

template<int MODE>
__global__ __launch_bounds__(256, 2) void gemm_fused(
    const ushort_t* __restrict__ A,
    const ushort_t* __restrict__ B1,
    const ushort_t* __restrict__ B2,
    float* __restrict__ C,
    const float* __restrict__ cosp, const float* __restrict__ sinp,
    int N, int K) {
    extern __shared__ char dsm[];
    const uint32_t tile = (smem_u32(dsm) + 127u) & ~127u;

    const int tid = threadIdx.x;
    const int wid = tid >> 5;
    const int lane = tid & 31;
    const int wm = wid & 3;
    const int wn = wid >> 2;
    const bool isV = (MODE == 2) && (blockIdx.x >= 4);
    const int bnx = isV ? ((int)blockIdx.x - 4) : (int)blockIdx.x;
    const int bm = blockIdx.y * 128;
    const int bn = bnx * 128;
    const ushort_t* Bm = isV ? B2 : B1;

    const int row = tid >> 1;
    const int half = tid & 1;
    const ushort_t* pA = A  + (size_t)(bm + row) * K + half * 16;
    const ushort_t* pB = Bm + (size_t)(bn + row) * K + half * 16;
    const uint32_t s_row = (uint32_t)(row * G_ROWB + half * 32);

    const int r8 = lane & 7, sub = lane >> 3;
    const uint32_t a_off = (uint32_t)((wm * 32 + r8 + (sub & 1) * 8) * G_ROWB +
                                      (sub >> 1) * 16);
    const uint32_t b_off = (uint32_t)((wn * 64 + r8 + (sub >> 1) * 8) * G_ROWB +
                                      (sub & 1) * 16);

    float acc[2][8][4];
#pragma unroll
    for (int i = 0; i < 2; i++)
#pragma unroll
        for (int j = 0; j < 8; j++)
#pragma unroll
            for (int q = 0; q < 4; q++) acc[i][j][q] = 0.f;

    const int nch = K >> 5;

#define G_ISSUE(chunk, sb) do {                                               \
    const int _k0 = (chunk) << 5;                                             \
    CP_ASYNC((sb) + s_row,              pA + _k0);                            \
    CP_ASYNC((sb) + s_row + 16,         pA + _k0 + 8);                        \
    CP_ASYNC((sb) + G_TILE + s_row,     pB + _k0);                            \
    CP_ASYNC((sb) + G_TILE + s_row + 16, pB + _k0 + 8);                       \
} while (0)

    G_ISSUE(0, tile);              CP_COMMIT();
    G_ISSUE(1, tile + G_STAGE_B);  CP_COMMIT();

    for (int i = 0; i < nch; i++) {
        const uint32_t cur = tile + (uint32_t)(i & 1) * G_STAGE_B;
        if (i + 1 < nch) { CP_WAIT1(); } else { CP_WAIT0(); }
        __syncthreads();

#pragma unroll
        for (int ks = 0; ks < 2; ks++) {
            uint32_t ah[8];
            const uint32_t ka = cur + a_off + ks * 32;
            ldm4(ah,     ka);
            ldm4(ah + 4, ka + 16 * G_ROWB);
#pragma unroll
            for (int g = 0; g < 4; g++) {
                uint32_t bh[4];
                ldm4(bh, cur + G_TILE + b_off + ks * 32 + g * (16 * G_ROWB));
#pragma unroll
                for (int ms = 0; ms < 2; ms++) {
                    mma16816h(acc[ms][2 * g],     ah + 4 * ms, bh[0], bh[1]);
                    mma16816h(acc[ms][2 * g + 1], ah + 4 * ms, bh[2], bh[3]);
                }
            }
        }
        __syncthreads();
        if (i + 2 < nch) {
            G_ISSUE(i + 2, cur);
            CP_COMMIT();
        }
    }
#undef G_ISSUE

    // ---------------- epilogues ----------------
    const int trow = lane >> 2;
    const int tcol = (lane & 3) * 2;

    if (MODE == 0) {
#pragma unroll
        for (int ms = 0; ms < 2; ms++) {
#pragma unroll
            for (int nf = 0; nf < 8; nf++) {
                const int r = bm + wm * 32 + ms * 16 + trow;
                const int c = bn + wn * 64 + nf * 8 + tcol;
                *(float2*)(C + (size_t)r * N + c) =
                    make_float2(acc[ms][nf][0], acc[ms][nf][1]);
                *(float2*)(C + (size_t)(r + 8) * N + c) =
                    make_float2(acc[ms][nf][2], acc[ms][nf][3]);
            }
        }
    } else {
        const int head = (bn + wn * 64) >> 6;
        const int nheads = (MODE == 1) ? NH : NKV;
        const float sc = (MODE == 1) ? (0.125f * 1.4426950408889634f) : 1.0f;
        ushort_t* gf = (MODE == 1) ? g_qf : (isV ? g_vf : g_kf);
#pragma unroll
        for (int ms = 0; ms < 2; ms++) {
#pragma unroll
            for (int q2 = 0; q2 < 2; q2++) {
                const int token = bm + wm * 32 + ms * 16 + trow + q2 * 8;
                const int bb = token >> 11;
                const int tt = token & (Tdim - 1);
                const size_t obase =
                    ((size_t)(bb * nheads + head) * Tdim + tt) * HD;
                if (isV) {
#pragma unroll
                    for (int nf = 0; nf < 8; nf++) {
#pragma unroll
                        for (int qc = 0; qc < 2; qc++) {
                            const int d = nf * 8 + tcol + qc;
                            gf[obase + d] = f16(acc[ms][nf][q2 * 2 + qc]);
                        }
                    }
                } else {
#pragma unroll
                    for (int nf = 0; nf < 4; nf++) {
#pragma unroll
                        for (int qc = 0; qc < 2; qc++) {
                            const int d = nf * 8 + tcol + qc;   // 0..31
                            float x1 = acc[ms][nf][q2 * 2 + qc];
                            float x2 = acc[ms][nf + 4][q2 * 2 + qc];
                            float c = cosp[(size_t)token * HD + d];
                            float s = sinp[(size_t)token * HD + d];
                            gf[obase + d]      = f16((x1 * c - x2 * s) * sc);
                            gf[obase + d + 32] = f16((x2 * c + x1 * s) * sc);
                        }
                    }
                }
            }
        }
    }
}

// ---------------- Flash attention (fp16 tensor cores, cp.async pipeline) ----
// Br=128, Bc=64, 256 threads (8 warps). Q resident fp16; K/V double-buffered.
#define FB 144
#define FA_SMEM ((9216 + 2 * 9216) * 2)   // 55296 bytes

__global__ __launch_bounds__(256, 2) void flash_mma() {
    extern __shared__ ushort_t fsm[];
    const uint32_t s0 = smem_u32(fsm);
    const uint32_t sQ = s0;

    const int tid = threadIdx.x;
    const int lane = tid & 31;
    const int w = tid >> 5;
    const int qtile = (int)gridDim.x - 1 - (int)blockIdx.x;  // big first
    const int bh = blockIdx.y;
    const int b = bh / NH;
    const int h = bh % NH;
    const int kvh = h / (NH / NKV);

    const ushort_t* qp = g_qf + ((size_t)bh * Tdim + qtile * 128) * HD;
    const size_t kvbase = (size_t)(b * NKV + kvh) * Tdim * HD;
    const ushort_t* pk = g_kf + kvbase;
    const ushort_t* pv = g_vf + kvbase;

    const uint32_t d0 = (uint32_t)((tid >> 3) * FB + (tid & 7) * 16);
    const uint32_t d1 = (uint32_t)(((tid + 256) >> 3) * FB + (tid & 7) * 16);
    const uint32_t g0 = (uint32_t)((tid >> 3) * HD + (tid & 7) * 8);
    const uint32_t g1 = (uint32_t)(((tid + 256) >> 3) * HD + (tid & 7) * 8);

#define FA_ISSUE(kt, stg) do {                                                \
    const uint32_t _sb = s0 + 18432 + (uint32_t)(stg) * 18432;                \
    const size_t _go = (size_t)(kt) * 64 * HD;                                \
    CP_ASYNC(_sb + d0,        pk + _go + g0);                                 \
    CP_ASYNC(_sb + d1,        pk + _go + g1);                                 \
    CP_ASYNC(_sb + 9216 + d0, pv + _go + g0);                                 \
    CP_ASYNC(_sb + 9216 + d1, pv + _go + g1);                                 \
} while (0)

    FA_ISSUE(0, 0); CP_COMMIT();
    FA_ISSUE(1, 1); CP_COMMIT();

    // stage Q (128x64 fp16)
#pragma unroll
    for (int j = 0; j < 4; j++) {
        const int idx = tid + j * 256;
        const int qr = idx >> 3;
        const int qc = idx & 7;
        *(uint4*)(fsm + qr * 72 + qc * 8) = *(const uint4*)(qp + qr * HD + qc * 8);
    }

    const int r8 = lane & 7, sub = lane >> 3;
    const uint32_t a_off = (uint32_t)((w * 16 + r8 + ((sub & 1) << 3)) * FB +
                                      ((sub >> 1) << 4));
    const uint32_t b_off = (uint32_t)((r8 + ((sub >> 1) << 3)) * FB +
                                      ((sub & 1) << 4));
    const uint32_t v_off = (uint32_t)(((lane & 8) + (lane & 7)) * FB +
                                      (lane >> 4) * 16);

    float m0 = -1e30f, m1 = -1e30f, l0 = 0.f, l1 = 0.f;
    float o[8][4];
#pragma unroll
    for (int t = 0; t < 8; t++)
#pragma unroll
        for (int e = 0; e < 4; e++) o[t][e] = 0.f;

    const int ktmax = 2 * qtile + 1;
    for (int kt = 0; kt <= ktmax; kt++) {
        const uint32_t stgK = s0 + 18432 + (uint32_t)(kt & 1) * 18432;
        const uint32_t stgV = stgK + 9216;
        if (kt < ktmax) { CP_WAIT1(); } else { CP_WAIT0(); }
        __syncthreads();

        // last tile: warps 0-3 fully above diagonal -> exact no-op
        if (kt < ktmax || w >= 4) {
            float sa[8][4];
#pragma unroll
            for (int t = 0; t < 8; t++)
#pragma unroll
                for (int e = 0; e < 4; e++) sa[t][e] = 0.f;

#pragma unroll
            for (int ks = 0; ks < 4; ks++) {
                uint32_t aq[4];
                ldm4(aq, sQ + a_off + ks * 32);
#pragma unroll
                for (int g = 0; g < 4; g++) {
                    uint32_t kb[4];
                    ldm4(kb, stgK + b_off + ks * 32 + g * (16 * FB));
                    mma16816h(sa[2 * g],     aq, kb[0], kb[1]);
                    mma16816h(sa[2 * g + 1], aq, kb[2], kb[3]);
                }
            }

            if (kt >= 2 * qtile) {
                const int row0 = qtile * 128 + w * 16 + (lane >> 2);
                const int cb = kt * 64 + (lane & 3) * 2;
#pragma unroll
                for (int t = 0; t < 8; t++) {
                    const int c0 = cb + t * 8;
                    if (c0 > row0)         sa[t][0] = -1e30f;
                    if (c0 + 1 > row0)     sa[t][1] = -1e30f;
                    if (c0 > row0 + 8)     sa[t][2] = -1e30f;
                    if (c0 + 1 > row0 + 8) sa[t][3] = -1e30f;
                }
            }

            float rm0 = -1e30f, rm1 = -1e30f;
#pragma unroll
            for (int t = 0; t < 8; t++) {
                rm0 = fmaxf(rm0, fmaxf(sa[t][0], sa[t][1]));
                rm1 = fmaxf(rm1, fmaxf(sa[t][2], sa[t][3]));
            }
            rm0 = fmaxf(rm0, __shfl_xor_sync(0xffffffffu, rm0, 1));
            rm0 = fmaxf(rm0, __shfl_xor_sync(0xffffffffu, rm0, 2));
            rm1 = fmaxf(rm1, __shfl_xor_sync(0xffffffffu, rm1, 1));
            rm1 = fmaxf(rm1, __shfl_xor_sync(0xffffffffu, rm1, 2));
            const float mn0 = fmaxf(m0, rm0);
            const float mn1 = fmaxf(m1, rm1);
            const float al0 = ex2(m0 - mn0);
            const float al1 = ex2(m1 - mn1);
            m0 = mn0; m1 = mn1;
            float rs0 = 0.f, rs1 = 0.f;
#pragma unroll
            for (int t = 0; t < 8; t++) {
                sa[t][0] = ex2(sa[t][0] - mn0);
                sa[t][1] = ex2(sa[t][1] - mn0);
                sa[t][2] = ex2(sa[t][2] - mn1);
                sa[t][3] = ex2(sa[t][3] - mn1);
                rs0 += sa[t][0] + sa[t][1];
                rs1 += sa[t][2] + sa[t][3];
            }
            rs0 += __shfl_xor_sync(0xffffffffu, rs0, 1);
            rs0 += __shfl_xor_sync(0xffffffffu, rs0, 2);
            rs1 += __shfl_xor_sync(0xffffffffu, rs1, 1);
            rs1 += __shfl_xor_sync(0xffffffffu, rs1, 2);
            l0 = l0 * al0 + rs0;
            l1 = l1 * al1 + rs1;
#pragma unroll
            for (int t = 0; t < 8; t++) {
                o[t][0] *= al0; o[t][1] *= al0;
                o[t][2] *= al1; o[t][3] *= al1;
            }

#pragma unroll
            for (int kc = 0; kc < 4; kc++) {
                const int t0 = 2 * kc, t1 = 2 * kc + 1;
                uint32_t ap[4];
                ap[0] = pack_f16(sa[t0][0], sa[t0][1]);
                ap[1] = pack_f16(sa[t0][2], sa[t0][3]);
                ap[2] = pack_f16(sa[t1][0], sa[t1][1]);
                ap[3] = pack_f16(sa[t1][2], sa[t1][3]);
#pragma unroll
                for (int tp = 0; tp < 4; tp++) {
                    uint32_t vb[4];
                    ldm4t(vb, stgV + v_off + kc * (16 * FB) + tp * 32);
                    mma16816h(o[2 * tp],     ap, vb[0], vb[1]);
                    mma16816h(o[2 * tp + 1], ap, vb[2], vb[3]);
                }
            }
        }

        __syncthreads();
        if (kt + 2 <= ktmax) {
            FA_ISSUE(kt + 2, kt & 1);
            CP_COMMIT();
        }
    }
#undef FA_ISSUE

    // epilogue: normalize + fp16 write for the O projection
    const float inv0 = 1.0f / l0;
    const float inv1 = 1.0f / l1;
    const int row0 = qtile * 128 + w * 16 + (lane >> 2);
    const int colb = (lane & 3) * 2;
#pragma unroll
    for (int t = 0; t < 8; t++) {
        const int c = h * HD + t * 8 + colb;
        const size_t i0 = ((size_t)b * Tdim + row0) * (NH * HD) + c;
        const size_t i1 = ((size_t)b * Tdim + row0 + 8) * (NH * HD) + c;
        *(uint32_t*)(g_of + i0) = pack_f16(o[t][0] * inv0, o[t][1] * inv0);
        *(uint32_t*)(g_of + i1) = pack_f16(o[t][2] * inv1, o[t][3] * inv1);
    }
}

// ---------------- launch ----------------------------------------------------
extern "C" void kernel_launch(void* const* d_in, const int* in_sizes, int n_in,
                              void* d_out, int out_size) {
    const float* hidden = (const float*)d_in[0];
    const float* cosp   = (const float*)d_in[1];
    const float* sinp   = (const float*)d_in[2];
    const float* wq     = (const float*)d_in[3];
    const float* wk     = (const float*)d_in[4];
    const float* wv     = (const float*)d_in[5];
    const float* wo     = (const float*)d_in[6];
    float* out = (float*)d_out;

    ushort_t *hf, *wqf, *wkf, *wvf, *wof, *of;
    cudaGetSymbolAddress((void**)&hf,  g_hf);
    cudaGetSymbolAddress((void**)&wqf, g_wqf);
    cudaGetSymbolAddress((void**)&wkf, g_wkf);
    cudaGetSymbolAddress((void**)&wvf, g_wvf);
    cudaGetSymbolAddress((void**)&wof, g_wof);
    cudaGetSymbolAddress((void**)&of,  g_of);

    cudaFuncSetAttribute(gemm_fused<0>, cudaFuncAttributeMaxDynamicSharedMemorySize, G_SMEM);
    cudaFuncSetAttribute(gemm_fused<1>, cudaFuncAttributeMaxDynamicSharedMemorySize, G_SMEM);
    cudaFuncSetAttribute(gemm_fused<2>, cudaFuncAttributeMaxDynamicSharedMemorySize, G_SMEM);
    cudaFuncSetAttribute(flash_mma, cudaFuncAttributeMaxDynamicSharedMemorySize, FA_SMEM);

    // fp32 -> fp16 converts
    cvt_f16<<<(BT * HID / 4 + 255) / 256, 256>>>(hidden, hf, BT * HID / 4);
    cvt_f16<<<(HID * HID / 4 + 255) / 256, 256>>>(wq, wqf, HID * HID / 4);
    cvt_f16<<<(NKV * HD * HID / 4 + 255) / 256, 256>>>(wk, wkf, NKV * HD * HID / 4);
    cvt_f16<<<(NKV * HD * HID / 4 + 255) / 256, 256>>>(wv, wvf, NKV * HD * HID / 4);
    cvt_f16<<<(HID * HID / 4 + 255) / 256, 256>>>(wo, wof, HID * HID / 4);

    // Q projection with fused rope+scale -> fp16
    gemm_fused<1><<<dim3(16, 32), 256, G_SMEM>>>(
        hf, wqf, nullptr, nullptr, cosp, sinp, NH * HD, HID);

    // K (rope) and V projections -> fp16, one launch
    gemm_fused<2><<<dim3(8, 32), 256, G_SMEM>>>(
        hf, wkf, wvf, nullptr, cosp, sinp, NKV * HD, HID);

    // Flash attention (fp16 tensor cores)
    flash_mma<<<dim3(Tdim / 128, Bdim * NH), 256, FA_SMEM>>>();

    // Output projection (fp16 single-term, fp32 epilogue)
    gemm_fused<0><<<dim3(16, 32), 256, G_SMEM>>>(
        of, wof, nullptr, out, nullptr, nullptr, HID, HID);
}

// round 15
// speedup vs baseline: 2.4408x; 1.0919x over previous
#include <cuda_runtime.h>
#include <cstdint>
#include <math.h>

#define Bdim 2
#define Tdim 2048
#define HID 2048
#define NH 32
#define NKV 8
#define HD 64
#define BT (Bdim * Tdim)   // 4096

typedef unsigned short ushort_t;

// ---------------- scratch (device globals; no allocations allowed) ----------
__device__ __align__(16) ushort_t g_hf [(size_t)BT * HID];
__device__ __align__(16) ushort_t g_wqf[(size_t)NH * HD * HID];
__device__ __align__(16) ushort_t g_wkf[(size_t)NKV * HD * HID];
__device__ __align__(16) ushort_t g_wvf[(size_t)NKV * HD * HID];
__device__ __align__(16) ushort_t g_wof[(size_t)HID * NH * HD];
__device__ __align__(16) ushort_t g_qf[(size_t)Bdim * NH  * Tdim * HD];
__device__ __align__(16) ushort_t g_kf[(size_t)Bdim * NKV * Tdim * HD];
__device__ __align__(16) ushort_t g_vf[(size_t)Bdim * NKV * Tdim * HD];
__device__ __align__(16) ushort_t g_of[(size_t)BT * NH * HD];

// ======================= helpers ============================================
static __device__ __forceinline__ uint32_t smem_u32(const void* p) {
    uint32_t a;
    asm("{ .reg .u64 t; cvta.to.shared.u64 t, %1; cvt.u32.u64 %0, t; }"
        : "=r"(a) : "l"(p));
    return a;
}

static __device__ __forceinline__ void ldm4(uint32_t* r, uint32_t addr) {
    asm volatile("ldmatrix.sync.aligned.m8n8.x4.shared.b16 {%0,%1,%2,%3}, [%4];"
                 : "=r"(r[0]), "=r"(r[1]), "=r"(r[2]), "=r"(r[3]) : "r"(addr));
}

static __device__ __forceinline__ void ldm4t(uint32_t* r, uint32_t addr) {
    asm volatile("ldmatrix.sync.aligned.m8n8.x4.trans.shared.b16 {%0,%1,%2,%3}, [%4];"
                 : "=r"(r[0]), "=r"(r[1]), "=r"(r[2]), "=r"(r[3]) : "r"(addr));
}

static __device__ __forceinline__ void mma16816h(float* c, const uint32_t* a,
                                                 uint32_t b0, uint32_t b1) {
    asm volatile("mma.sync.aligned.m16n8k16.row.col.f32.f16.f16.f32 "
                 "{%0,%1,%2,%3}, {%4,%5,%6,%7}, {%8,%9}, {%0,%1,%2,%3};"
                 : "+f"(c[0]), "+f"(c[1]), "+f"(c[2]), "+f"(c[3])
                 : "r"(a[0]), "r"(a[1]), "r"(a[2]), "r"(a[3]), "r"(b0), "r"(b1));
}

static __device__ __forceinline__ uint32_t pack_f16(float a, float b) {
    uint32_t r;
    asm("cvt.rn.f16x2.f32 %0, %1, %2;" : "=r"(r) : "f"(b), "f"(a));
    return r;
}
static __device__ __forceinline__ ushort_t f16(float x) {
    ushort_t r;
    asm("cvt.rn.f16.f32 %0, %1;" : "=h"(r) : "f"(x));
    return r;
}

static __device__ __forceinline__ float ex2(float x) {
    float r;
    asm("ex2.approx.f32 %0, %1;" : "=f"(r) : "f"(x));
    return r;
}

#define CP_ASYNC(dst, src) \
    asm volatile("cp.async.cg.shared.global [%0], [%1], 16;" \
                 :: "r"(dst), "l"(src) : "memory")
#define CP_COMMIT() asm volatile("cp.async.commit_group;" ::: "memory")
#define CP_WAIT1() asm volatile("cp.async.wait_group 1;" ::: "memory")
#define CP_WAIT0() asm volatile("cp.async.wait_group 0;" ::: "memory")

// ---------------- merged fp32 -> fp16 convert --------------------------------
#define CV_N0 (BT * HID / 4)           // hidden
#define CV_N1 (HID * HID / 4)          // wq
#define CV_N2 (NKV * HD * HID / 4)     // wk
#define CV_N3 (NKV * HD * HID / 4)     // wv
#define CV_N4 (HID * HID / 4)          // wo
#define CV_TOT (CV_N0 + CV_N1 + CV_N2 + CV_N3 + CV_N4)

__global__ __launch_bounds__(256) void cvt_all(
    const float* __restrict__ h,  const float* __restrict__ wq,
    const float* __restrict__ wk, const float* __restrict__ wv,
    const float* __restrict__ wo) {
    int i = blockIdx.x * blockDim.x + threadIdx.x;
    const float* src;
    ushort_t* dst;
    if (i < CV_N0)                      { src = h;  dst = g_hf; }
    else if ((i -= CV_N0) < CV_N1)      { src = wq; dst = g_wqf; }
    else if ((i -= CV_N1) < CV_N2)      { src = wk; dst = g_wkf; }
    else if ((i -= CV_N2) < CV_N3)      { src = wv; dst = g_wvf; }
    else if ((i -= CV_N3) < CV_N4)      { src = wo; dst = g_wof; }
    else return;
    float4 f = ((const float4*)src)[i];
    ((uint2*)dst)[i] = make_uint2(pack_f16(f.x, f.y), pack_f16(f.z, f.w));
}

// =============== fp16 mma.sync GEMM, 3-stage pipeline, fused epilogues ======
// MODE 0: O projection, fp32 C store (grid 16x32).
// MODE 1: merged QKV (grid 24x32): x<16 Q(rope+scale), 16-19 K(rope), 20-23 V.
#define G_ROWB 80
#define G_TILE 10240
#define G_STAGE_B (2 * G_TILE)              // 20480
#define G_SMEM (3 * G_STAGE_B + 128)        // 61568

template<int MODE>
__global__ __launch_bounds__(256, 2) void gemm_fused(
    const ushort_t* __restrict__ A,
    const ushort_t* __restrict__ B1,
    const ushort_t* __restrict__ B2,
    const ushort_t* __restrict__ B3,
    float* __restrict__ C,
    const float* __restrict__ cosp, const float* __restrict__ sinp,
    int K) {
    extern __shared__ char dsm[];
    const uint32_t tile = (smem_u32(dsm) + 127u) & ~127u;

    const int tid = threadIdx.x;
    const int wid = tid >> 5;
    const int lane = tid & 31;
    const int wm = wid & 3;
    const int wn = wid >> 2;

    const bool isQ = (MODE == 0) || (blockIdx.x < 16);
    const bool isV = (MODE == 1) && (blockIdx.x >= 20);
    const int bnx = (MODE == 0) ? (int)blockIdx.x
                   : (blockIdx.x < 16 ? (int)blockIdx.x
                      : (isV ? (int)blockIdx.x - 20 : (int)blockIdx.x - 16));
    const int bm = blockIdx.y * 128;
    const int bn = bnx * 128;
    const ushort_t* Bm = (MODE == 0) ? B1
                        : (blockIdx.x < 16 ? B1 : (isV ? B3 : B2));

    const int row = tid >> 1;
    const int half = tid & 1;
    const ushort_t* pA = A  + (size_t)(bm + row) * K + half * 16;
    const ushort_t* pB = Bm + (size_t)(bn + row) * K + half * 16;
    const uint32_t s_row = (uint32_t)(row * G_ROWB + half * 32);

    const int r8 = lane & 7, sub = lane >> 3;
    const uint32_t a_off = (uint32_t)((wm * 32 + r8 + (sub & 1) * 8) * G_ROWB +
                                      (sub >> 1) * 16);
    const uint32_t b_off = (uint32_t)((wn * 64 + r8 + (sub >> 1) * 8) * G_ROWB +
                                      (sub & 1) * 16);

    float acc[2][8][4];
#pragma unroll
    for (int i = 0; i < 2; i++)
#pragma unroll
        for (int j = 0; j < 8; j++)
#pragma unroll
            for (int q = 0; q < 4; q++) acc[i][j][q] = 0.f;

    const int nch = K >> 5;

#define G_ISSUE(chunk, sb) do {                                               \
    const int _k0 = (chunk) << 5;                                             \
    CP_ASYNC((sb) + s_row,               pA + _k0);                           \
    CP_ASYNC((sb) + s_row + 16,          pA + _k0 + 8);                       \
    CP_ASYNC((sb) + G_TILE + s_row,      pB + _k0);                           \
    CP_ASYNC((sb) + G_TILE + s_row + 16, pB + _k0 + 8);                       \
} while (0)

    G_ISSUE(0, tile);              CP_COMMIT();
    G_ISSUE(1, tile + G_STAGE_B);  CP_COMMIT();

    int st = 0;                         // i % 3
    for (int i = 0; i < nch; i++) {
        const uint32_t cur = tile + (uint32_t)st * G_STAGE_B;
        if (i + 1 < nch) { CP_WAIT1(); } else { CP_WAIT0(); }
        __syncthreads();
        // issue chunk i+2 into stage (i+2)%3 — freed by compute(i-1),
        // which the barrier above just proved complete.
        if (i + 2 < nch) {
            int st2 = st + 2; if (st2 >= 3) st2 -= 3;
            G_ISSUE(i + 2, tile + (uint32_t)st2 * G_STAGE_B);
            CP_COMMIT();
        }

#pragma unroll
        for (int ks = 0; ks < 2; ks++) {
            uint32_t ah[8];
            const uint32_t ka = cur + a_off + ks * 32;
            ldm4(ah,     ka);
            ldm4(ah + 4, ka + 16 * G_ROWB);
#pragma unroll
            for (int g = 0; g < 4; g++) {
                uint32_t bh[4];
                ldm4(bh, cur + G_TILE + b_off + ks * 32 + g * (16 * G_ROWB));
#pragma unroll
                for (int ms = 0; ms < 2; ms++) {
                    mma16816h(acc[ms][2 * g],     ah + 4 * ms, bh[0], bh[1]);
                    mma16816h(acc[ms][2 * g + 1], ah + 4 * ms, bh[2], bh[3]);
                }
            }
        }
        if (++st == 3) st = 0;
    }
#undef G_ISSUE

    // ---------------- epilogues ----------------
    const int trow = lane >> 2;
    const int tcol = (lane & 3) * 2;

    if (MODE == 0) {
#pragma unroll
        for (int ms = 0; ms < 2; ms++) {
#pragma unroll
            for (int nf = 0; nf < 8; nf++) {
                const int r = bm + wm * 32 + ms * 16 + trow;
                const int c = bn + wn * 64 + nf * 8 + tcol;
                *(float2*)(C + (size_t)r * HID + c) =
                    make_float2(acc[ms][nf][0], acc[ms][nf][1]);
                *(float2*)(C + (size_t)(r + 8) * HID + c) =
                    make_float2(acc[ms][nf][2], acc[ms][nf][3]);
            }
        }
    } else {
        const int head = (bn + wn * 64) >> 6;
        const int nheads = isQ ? NH : NKV;
        const float sc = isQ ? (0.125f * 1.4426950408889634f) : 1.0f;
        ushort_t* gf = isQ ? g_qf : (isV ? g_vf : g_kf);
#pragma unroll
        for (int ms = 0; ms < 2; ms++) {
#pragma unroll
            for (int q2 = 0; q2 < 2; q2++) {
                const int token = bm + wm * 32 + ms * 16 + trow + q2 * 8;
                const int bb = token >> 11;
                const int tt = token & (Tdim - 1);
                const size_t obase =
                    ((size_t)(bb * nheads + head) * Tdim + tt) * HD;
                if (isV) {
#pragma unroll
                    for (int nf = 0; nf < 8; nf++) {
#pragma unroll
                        for (int qc = 0; qc < 2; qc++) {
                            const int d = nf * 8 + tcol + qc;
                            gf[obase + d] = f16(acc[ms][nf][q2 * 2 + qc]);
                        }
                    }
                } else {
#pragma unroll
                    for (int nf = 0; nf < 4; nf++) {
#pragma unroll
                        for (int qc = 0; qc < 2; qc++) {
                            const int d = nf * 8 + tcol + qc;   // 0..31
                            float x1 = acc[ms][nf][q2 * 2 + qc];
                            float x2 = acc[ms][nf + 4][q2 * 2 + qc];
                            float c = cosp[(size_t)token * HD + d];
                            float s = sinp[(size_t)token * HD + d];
                            gf[obase + d]      = f16((x1 * c - x2 * s) * sc);
                            gf[obase + d + 32] = f16((x2 * c + x1 * s) * sc);
                        }
                    }
                }
            }
        }
    }
}

// ---------------- Flash attention (fp16, 3-stage cp.async pipeline) ---------
// Br=128, Bc=64, 256 threads (8 warps). Q resident; K/V triple-buffered.
// smem bytes: Q [0,18432); stage s at 18432 + s*18432 (K 9216 | V 9216).
#define FB 144
#define FA_SMEM (4 * 18432)   // 73728

__global__ __launch_bounds__(256, 2) void flash_mma() {
    extern __shared__ ushort_t fsm[];
    const uint32_t s0 = smem_u32(fsm);
    const uint32_t sQ = s0;

    const int tid = threadIdx.x;
    const int lane = tid & 31;
    const int w = tid >> 5;
    const int qtile = (int)gridDim.x - 1 - (int)blockIdx.x;  // big first
    const int bh = blockIdx.y;
    const int b = bh / NH;
    const int h = bh % NH;
    const int kvh = h / (NH / NKV);

    const ushort_t* qp = g_qf + ((size_t)bh * Tdim + qtile * 128) * HD;
    const size_t kvbase = (size_t)(b * NKV + kvh) * Tdim * HD;
    const ushort_t* pk = g_kf + kvbase;
    const ushort_t* pv = g_vf + kvbase;

    const uint32_t d0 = (uint32_t)((tid >> 3) * FB + (tid & 7) * 16);
    const uint32_t d1 = (uint32_t)(((tid + 256) >> 3) * FB + (tid & 7) * 16);
    const uint32_t g0 = (uint32_t)((tid >> 3) * HD + (tid & 7) * 8);
    const uint32_t g1 = (uint32_t)(((tid + 256) >> 3) * HD + (tid & 7) * 8);

#define FA_ISSUE(kt, stg) do {                                                \
    const uint32_t _sb = s0 + 18432 + (uint32_t)(stg) * 18432;                \
    const size_t _go = (size_t)(kt) * 64 * HD;                                \
    CP_ASYNC(_sb + d0,        pk + _go + g0);                                 \
    CP_ASYNC(_sb + d1,        pk + _go + g1);                                 \
    CP_ASYNC(_sb + 9216 + d0, pv + _go + g0);                                 \
    CP_ASYNC(_sb + 9216 + d1, pv + _go + g1);                                 \
} while (0)

    FA_ISSUE(0, 0); CP_COMMIT();
    FA_ISSUE(1, 1); CP_COMMIT();

    // stage Q (128x64 fp16)
#pragma unroll
    for (int j = 0; j < 4; j++) {
        const int idx = tid + j * 256;
        const int qr = idx >> 3;
        const int qc = idx & 7;
        *(uint4*)(fsm + qr * 72 + qc * 8) = *(const uint4*)(qp + qr * HD + qc * 8);
    }

    const int r8 = lane & 7, sub = lane >> 3;
    const uint32_t a_off = (uint32_t)((w * 16 + r8 + ((sub & 1) << 3)) * FB +
                                      ((sub >> 1) << 4));
    const uint32_t b_off = (uint32_t)((r8 + ((sub >> 1) << 3)) * FB +
                                      ((sub & 1) << 4));
    const uint32_t v_off = (uint32_t)(((lane & 8) + (lane & 7)) * FB +
                                      (lane >> 4) * 16);

    float m0 = -1e30f, m1 = -1e30f, l0 = 0.f, l1 = 0.f;
    float o[8][4];
#pragma unroll
    for (int t = 0; t < 8; t++)
#pragma unroll
        for (int e = 0; e < 4; e++) o[t][e] = 0.f;

    const int ktmax = 2 * qtile + 1;
    int st = 0;                           // kt % 3
    for (int kt = 0; kt <= ktmax; kt++) {
        const uint32_t stgK = s0 + 18432 + (uint32_t)st * 18432;
        const uint32_t stgV = stgK + 9216;
        if (kt < ktmax) { CP_WAIT1(); } else { CP_WAIT0(); }
        __syncthreads();
        if (kt + 2 <= ktmax) {
            int st2 = st + 2; if (st2 >= 3) st2 -= 3;
            FA_ISSUE(kt + 2, st2);
            CP_COMMIT();
        }

        // last tile: warps 0-3 fully above diagonal -> exact no-op
        if (kt < ktmax || w >= 4) {
            float sa[8][4];
#pragma unroll
            for (int t = 0; t < 8; t++)
#pragma unroll
                for (int e = 0; e < 4; e++) sa[t][e] = 0.f;

#pragma unroll
            for (int ks = 0; ks < 4; ks++) {
                uint32_t aq[4];
                ldm4(aq, sQ + a_off + ks * 32);
#pragma unroll
                for (int g = 0; g < 4; g++) {
                    uint32_t kb[4];
                    ldm4(kb, stgK + b_off + ks * 32 + g * (16 * FB));
                    mma16816h(sa[2 * g],     aq, kb[0], kb[1]);
                    mma16816h(sa[2 * g + 1], aq, kb[2], kb[3]);
                }
            }

            if (kt >= 2 * qtile) {
                const int row0 = qtile * 128 + w * 16 + (lane >> 2);
                const int cb = kt * 64 + (lane & 3) * 2;
#pragma unroll
                for (int t = 0; t < 8; t++) {
                    const int c0 = cb + t * 8;
                    if (c0 > row0)         sa[t][0] = -1e30f;
                    if (c0 + 1 > row0)     sa[t][1] = -1e30f;
                    if (c0 > row0 + 8)     sa[t][2] = -1e30f;
                    if (c0 + 1 > row0 + 8) sa[t][3] = -1e30f;
                }
            }

            float rm0 = -1e30f, rm1 = -1e30f;
#pragma unroll
            for (int t = 0; t < 8; t++) {
                rm0 = fmaxf(rm0, fmaxf(sa[t][0], sa[t][1]));
                rm1 = fmaxf(rm1, fmaxf(sa[t][2], sa[t][3]));
            }
            rm0 = fmaxf(rm0, __shfl_xor_sync(0xffffffffu, rm0, 1));
            rm0 = fmaxf(rm0, __shfl_xor_sync(0xffffffffu, rm0, 2));
            rm1 = fmaxf(rm1, __shfl_xor_sync(0xffffffffu, rm1, 1));
            rm1 = fmaxf(rm1, __shfl_xor_sync(0xffffffffu, rm1, 2));
            const float mn0 = fmaxf(m0, rm0);
            const float mn1 = fmaxf(m1, rm1);
            const float al0 = ex2(m0 - mn0);
            const float al1 = ex2(m1 - mn1);
            m0 = mn0; m1 = mn1;
            float rs0 = 0.f, rs1 = 0.f;
#pragma unroll
            for (int t = 0; t < 8; t++) {
                sa[t][0] = ex2(sa[t][0] - mn0);
                sa[t][1] = ex2(sa[t][1] - mn0);
                sa[t][2] = ex2(sa[t][2] - mn1);
                sa[t][3] = ex2(sa[t][3] - mn1);
                rs0 += sa[t][0] + sa[t][1];
                rs1 += sa[t][2] + sa[t][3];
            }
            rs0 += __shfl_xor_sync(0xffffffffu, rs0, 1);
            rs0 += __shfl_xor_sync(0xffffffffu, rs0, 2);
            rs1 += __shfl_xor_sync(0xffffffffu, rs1, 1);
            rs1 += __shfl_xor_sync(0xffffffffu, rs1, 2);
            l0 = l0 * al0 + rs0;
            l1 = l1 * al1 + rs1;
#pragma unroll
            for (int t = 0; t < 8; t++) {
                o[t][0] *= al0; o[t][1] *= al0;
                o[t][2] *= al1; o[t][3] *= al1;
            }

#pragma unroll
            for (int kc = 0; kc < 4; kc++) {
                const int t0 = 2 * kc, t1 = 2 * kc + 1;
                uint32_t ap[4];
                ap[0] = pack_f16(sa[t0][0], sa[t0][1]);
                ap[1] = pack_f16(sa[t0][2], sa[t0][3]);
                ap[2] = pack_f16(sa[t1][0], sa[t1][1]);
                ap[3] = pack_f16(sa[t1][2], sa[t1][3]);
#pragma unroll
                for (int tp = 0; tp < 4; tp++) {
                    uint32_t vb[4];
                    ldm4t(vb, stgV + v_off + kc * (16 * FB) + tp * 32);
                    mma16816h(o[2 * tp],     ap, vb[0], vb[1]);
                    mma16816h(o[2 * tp + 1], ap, vb[2], vb[3]);
                }
            }
        }
        if (++st == 3) st = 0;
    }
#undef FA_ISSUE

    // epilogue: normalize + fp16 write for the O projection
    const float inv0 = 1.0f / l0;
    const float inv1 = 1.0f / l1;
    const int row0 = qtile * 128 + w * 16 + (lane >> 2);
    const int colb = (lane & 3) * 2;
#pragma unroll
    for (int t = 0; t < 8; t++) {
        const int c = h * HD + t * 8 + colb;
        const size_t i0 = ((size_t)b * Tdim + row0) * (NH * HD) + c;
        const size_t i1 = ((size_t)b * Tdim + row0 + 8) * (NH * HD) + c;
        *(uint32_t*)(g_of + i0) = pack_f16(o[t][0] * inv0, o[t][1] * inv0);
        *(uint32_t*)(g_of + i1) = pack_f16(o[t][2] * inv1, o[t][3] * inv1);
    }
}

// ---------------- launch ----------------------------------------------------
extern "C" void kernel_launch(void* const* d_in, const int* in_sizes, int n_in,
                              void* d_out, int out_size) {
    const float* hidden = (const float*)d_in[0];
    const float* cosp   = (const float*)d_in[1];
    const float* sinp   = (const float*)d_in[2];
    const float* wq     = (const float*)d_in[3];
    const float* wk     = (const float*)d_in[4];
    const float* wv     = (const float*)d_in[5];
    const float* wo     = (const float*)d_in[6];
    float* out = (float*)d_out;

    ushort_t *hf, *wqf, *wkf, *wvf, *wof, *of;
    cudaGetSymbolAddress((void**)&hf,  g_hf);
    cudaGetSymbolAddress((void**)&wqf, g_wqf);
    cudaGetSymbolAddress((void**)&wkf, g_wkf);
    cudaGetSymbolAddress((void**)&wvf, g_wvf);
    cudaGetSymbolAddress((void**)&wof, g_wof);
    cudaGetSymbolAddress((void**)&of,  g_of);

    cudaFuncSetAttribute(gemm_fused<0>, cudaFuncAttributeMaxDynamicSharedMemorySize, G_SMEM);
    cudaFuncSetAttribute(gemm_fused<1>, cudaFuncAttributeMaxDynamicSharedMemorySize, G_SMEM);
    cudaFuncSetAttribute(flash_mma, cudaFuncAttributeMaxDynamicSharedMemorySize, FA_SMEM);

    // merged fp32 -> fp16 converts
    cvt_all<<<(CV_TOT + 255) / 256, 256>>>(hidden, wq, wk, wv, wo);

    // merged Q/K/V projections (Q: rope+scale, K: rope, V: plain) -> fp16
    gemm_fused<1><<<dim3(24, 32), 256, G_SMEM>>>(
        hf, wqf, wkf, wvf, nullptr, cosp, sinp, HID);

    // Flash attention (fp16 tensor cores)
    flash_mma<<<dim3(Tdim / 128, Bdim * NH), 256, FA_SMEM>>>();

    // Output projection (fp16, fp32 epilogue)
    gemm_fused<0><<<dim3(16, 32), 256, G_SMEM>>>(
        of, wof, nullptr, nullptr, out, nullptr, nullptr, HID);
}